// round 13
// baseline (speedup 1.0000x reference)
#include <cuda_runtime.h>
#include <cuda_bf16.h>
#include <cstdint>

// ---------------------------------------------------------------------------
// ChebGcnDecoder, commuted form. All big GEMMs on mma.sync bf16 hi/lo 3-split
// with pre-split bf16 inputs, cp.async double-buffered smem. R13: FC2 and L0
// use a 128x128 block tile (64x32 warp tiles, MMA:LDSM = 4:1, 16 independent
// acc chains); L1-L3 keep the 128x64 tile. CSR build fused (5 launches).
// ---------------------------------------------------------------------------

#define LRELU_S 0.2f

__device__ float g_T[42467328];            // U0|U1|U2, stride Mg*co
__device__ float g_outA[14155776];         // fp32 layer output (l=3)
__device__ float g_Y[14155776];            // Y = U1 + 2*P*U2
__device__ __nv_bfloat16 g_Ah[14155776];   // bf16-hi GEMM input (activations)
__device__ __nv_bfloat16 g_Al[14155776];   // bf16-lo
__device__ __nv_bfloat16 g_w2h[56623104];  // fc_w2 transposed+split (N x K)
__device__ __nv_bfloat16 g_w2l[56623104];
__device__ float g_h1[65536];              // FC1 output 128x512 fp32
__device__ __nv_bfloat16 g_h1h[65536];
__device__ __nv_bfloat16 g_h1l[65536];
__device__ float g_wc[49152];              // combined weights fp32 (K x N), L4
__device__ __nv_bfloat16 g_wth[49152];     // combined weights bf16-hi (Np x K)
__device__ __nv_bfloat16 g_wtl[49152];
__device__ int   g_cnt[12960];
__device__ float g_dinv[12960];
__device__ int   g_off[12961];
__device__ int   g_cur[12960];
__device__ int   g_csrc[77760];
__device__ float g_cw[77760];
__device__ int   g_is64;

__constant__ int c_nb[4] = {0, 864, 2592, 6048};
__constant__ int c_eb[4] = {0, 5184, 15552, 36288};
__constant__ int c_nl[4] = {864, 1728, 3456, 6912};

// ---------------------------------------------------------------------------
__device__ __forceinline__ int read_idx(const void* p, int i) {
    if (g_is64) return (int)((const long long*)p)[i];
    return ((const int*)p)[i];
}

__global__ void detect_kernel(const int* w, int nwords) {
    __shared__ int any;
    if (threadIdx.x == 0) any = 0;
    __syncthreads();
    int a = 0;
    for (int i = 1 + 2 * (int)threadIdx.x; i < nwords; i += 2 * blockDim.x) a |= w[i];
    if (a) atomicOr(&any, 1);
    __syncthreads();
    if (threadIdx.x == 0) g_is64 = any ? 0 : 1;
}

// ---- fused CSR build over all 4 graphs ----
__global__ void csr_zero_kernel() {
    int i = blockIdx.x * blockDim.x + threadIdx.x;
    if (i < 12960) g_cnt[i] = 0;
}

__global__ void csr_count_kernel(const void* e0, const void* e1,
                                 const void* e2, const void* e3) {
    int l = blockIdx.y;
    const void* eg = (l == 0) ? e0 : (l == 1) ? e1 : (l == 2) ? e2 : e3;
    int e = 6 * c_nl[l];
    int i = blockIdx.x * blockDim.x + threadIdx.x;
    if (i < e) atomicAdd(&g_cnt[c_nb[l] + read_idx(eg, e + i)], 1);
}

__global__ void csr_dinv_kernel() {
    int i = blockIdx.x * blockDim.x + threadIdx.x;
    if (i < 12960) g_dinv[i] = (g_cnt[i] > 0) ? rsqrtf((float)g_cnt[i]) : 0.0f;
}

__global__ void csr_scan_kernel() {
    __shared__ int partial[1024];
    int l = blockIdx.x;
    int n = c_nl[l], nb = c_nb[l], eb = c_eb[l];
    int tid = threadIdx.x;
    int C = (n + 1023) / 1024;
    int start = tid * C;
    int local[8];
    int s = 0;
    for (int i = 0; i < C; i++) {
        int idx = start + i;
        int v = (idx < n) ? g_cnt[nb + idx] : 0;
        local[i] = s;
        s += v;
    }
    partial[tid] = s;
    __syncthreads();
    for (int d = 1; d < 1024; d <<= 1) {
        int t = (tid >= d) ? partial[tid - d] : 0;
        __syncthreads();
        if (tid >= d) partial[tid] += t;
        __syncthreads();
    }
    int base = (tid > 0) ? partial[tid - 1] : 0;
    for (int i = 0; i < C; i++) {
        int idx = start + i;
        if (idx < n) {
            int o = eb + base + local[i];
            g_off[nb + idx] = o;
            g_cur[nb + idx] = o;
        }
    }
    if (l == 3 && tid == 1023) g_off[12960] = 77760;
}

__global__ void csr_fill_kernel(const void* e0, const void* e1,
                                const void* e2, const void* e3) {
    int l = blockIdx.y;
    const void* eg = (l == 0) ? e0 : (l == 1) ? e1 : (l == 2) ? e2 : e3;
    int e = 6 * c_nl[l];
    int nb = c_nb[l];
    int i = blockIdx.x * blockDim.x + threadIdx.x;
    if (i < e) {
        int s = read_idx(eg, i);
        int d = read_idx(eg, e + i);
        int p = atomicAdd(&g_cur[nb + d], 1);
        g_csrc[p] = s;
        g_cw[p] = -g_dinv[nb + s] * g_dinv[nb + d];
    }
}

// Combined weights [W0-W2 | W1 | W2]: fp32 (K x N) for SIMT L4, bf16 hi/lo
// transposed (Np x K) for the mma path. Factor 2 on P^2 applied in props.
__global__ void wprep_kernel(const float* __restrict__ W,
                             float* __restrict__ Wc,
                             __nv_bfloat16* __restrict__ Wth,
                             __nv_bfloat16* __restrict__ Wtl,
                             int ci, int co, int Np) {
    int i = blockIdx.x * blockDim.x + threadIdx.x;
    int N = 3 * co;
    if (i >= Np * ci) return;
    int n = i / ci, k = i - n * ci;
    int cico = ci * co;
    float v = 0.f;
    if (n < N) {
        if (n < co)            v = W[k * co + n] - W[2 * cico + k * co + n];
        else if (n < 2 * co)   v = W[cico + k * co + (n - co)];
        else                   v = W[2 * cico + k * co + (n - 2 * co)];
        Wc[k * N + n] = v;
    }
    __nv_bfloat16 h = __float2bfloat16(v);
    Wth[n * ci + k] = h;
    Wtl[n * ci + k] = __float2bfloat16(v - __bfloat162float(h));
}

// fc_w2 (K=512 x N=110592) fp32 -> transposed (N x K) bf16 hi/lo.
__global__ void tsplit_kernel(const float* __restrict__ in,
                              __nv_bfloat16* __restrict__ outh,
                              __nv_bfloat16* __restrict__ outl) {
    __shared__ float t[32][33];
    const int N = 110592, K = 512;
    int n0 = blockIdx.x * 32, k0 = blockIdx.y * 32;
    int tx = threadIdx.x, ty = threadIdx.y;
#pragma unroll
    for (int i = 0; i < 4; i++)
        t[ty + 8 * i][tx] = in[(size_t)(k0 + ty + 8 * i) * N + n0 + tx];
    __syncthreads();
#pragma unroll
    for (int i = 0; i < 4; i++) {
        float v = t[tx][ty + 8 * i];
        __nv_bfloat16 h = __float2bfloat16(v);
        size_t o = (size_t)(n0 + ty + 8 * i) * K + k0 + tx;
        outh[o] = h;
        outl[o] = __float2bfloat16(v - __bfloat162float(h));
    }
}

// split FC1 output (128x512) into bf16 hi/lo
__global__ void hsplit_kernel(const float* __restrict__ in,
                              __nv_bfloat16* __restrict__ outh,
                              __nv_bfloat16* __restrict__ outl) {
    int i = blockIdx.x * blockDim.x + threadIdx.x;
    if (i < 65536) {
        float v = in[i];
        __nv_bfloat16 h = __float2bfloat16(v);
        outh[i] = h;
        outl[i] = __float2bfloat16(v - __bfloat162float(h));
    }
}

// ---------------------------------------------------------------------------
__device__ __forceinline__ uint32_t smem_u32(const void* p) {
    uint32_t a;
    asm("{ .reg .u64 t; cvta.to.shared.u64 t, %1; cvt.u32.u64 %0, t; }"
        : "=r"(a) : "l"(p));
    return a;
}

__device__ __forceinline__ void cp_async16(uint32_t dst, const void* src) {
    asm volatile("cp.async.cg.shared.global [%0], [%1], 16;"
                 :: "r"(dst), "l"(src));
}

#define LDSM_X4(r0, r1, r2, r3, a)                                            \
    asm volatile("ldmatrix.sync.aligned.m8n8.x4.shared.b16 {%0,%1,%2,%3}, [%4];" \
        : "=r"(r0), "=r"(r1), "=r"(r2), "=r"(r3) : "r"(a))

#define MMA4(c, a, b0, b1)                                                    \
    asm volatile(                                                             \
        "mma.sync.aligned.m16n8k16.row.col.f32.bf16.bf16.f32 "                \
        "{%0,%1,%2,%3}, {%4,%5,%6,%7}, {%8,%9}, {%0,%1,%2,%3};\n"             \
        : "+f"((c)[0]), "+f"((c)[1]), "+f"((c)[2]), "+f"((c)[3])              \
        : "r"((a)[0]), "r"((a)[1]), "r"((a)[2]), "r"((a)[3]),                 \
          "r"(b0), "r"(b1))

// shared epilogue element write
template<int EPI>
__device__ __forceinline__ void epi_write(float v, int m, int n, int N,
                                          const float* bias, float* out,
                                          __nv_bfloat16* outh, __nv_bfloat16* outl,
                                          int coLog2, long long ustr) {
    if (n >= N) return;
    if (EPI == 0) {
        int t = n >> coLog2;
        int cc = n & ((1 << coLog2) - 1);
        out[(size_t)t * (size_t)ustr + ((size_t)m << coLog2) + cc] = v;
    } else {
        v += bias[n];
        __nv_bfloat16 h = __float2bfloat16(v);
        size_t o = (size_t)((n >> 7) * 128 + m) * 128 + (n & 127);
        outh[o] = h;
        outl[o] = __float2bfloat16(v - __bfloat162float(h));
    }
}

// ---------------------------------------------------------------------------
// 128x128-tile bf16 GEMM (FC2, L0): 8 warps 2x4 grid, 64x32 warp tiles.
// KC=64, double-buffered (4 x 16KB banks per buffer = 64KB, 128KB total).
// ---------------------------------------------------------------------------
#define GBUF2 65536

template<int EPI>
__global__ __launch_bounds__(256)
void gemm_mmab128(const __nv_bfloat16* __restrict__ Ah, const __nv_bfloat16* __restrict__ Al,
                  const __nv_bfloat16* __restrict__ Wh, const __nv_bfloat16* __restrict__ Wl,
                  const float* __restrict__ bias, float* __restrict__ out,
                  __nv_bfloat16* __restrict__ outh, __nv_bfloat16* __restrict__ outl,
                  int M, int N, int K, int coLog2, long long ustr) {
    extern __shared__ __align__(128) uint8_t smdyn[];
    const uint32_t sb = smem_u32(smdyn);
    const uint32_t oAh = 0, oAl = 16384, oBh = 32768, oBl = 49152;

    const int tid = threadIdx.x, lane = tid & 31, warp = tid >> 5;
    const int wm = warp & 1, wn = warp >> 1;   // 2 x 4 warp grid, 64x32 tiles
    const int m0 = blockIdx.y * 128, n0 = blockIdx.x * 128;

    float acc[4][4][4];
#pragma unroll
    for (int i = 0; i < 4; i++)
#pragma unroll
        for (int j = 0; j < 4; j++)
#pragma unroll
            for (int q = 0; q < 4; q++) acc[i][j][q] = 0.f;

    const uint32_t lq = lane >> 3, lr = lane & 7;
    const uint32_t qk = (lq >> 1) << 4;
    uint32_t aoff[4], asw[4], boff[2], bsw[2];
#pragma unroll
    for (int mt = 0; mt < 4; mt++) {
        int row = wm * 64 + mt * 16 + ((lq & 1) << 3) + lr;
        aoff[mt] = (uint32_t)row * 128;
        asw[mt] = (uint32_t)((row & 7) << 4);
    }
#pragma unroll
    for (int nt = 0; nt < 2; nt++) {
        int row = wn * 32 + nt * 16 + ((lq & 1) << 3) + lr;
        boff[nt] = (uint32_t)row * 128;
        bsw[nt] = (uint32_t)((row & 7) << 4);
    }

    const int nstages = K >> 6;   // KC = 64

#define PREFETCH2(S, BUF) do {                                                \
        int k0_ = (S) << 6;                                                   \
        uint32_t bo_ = sb + (BUF) * GBUF2;                                    \
        _Pragma("unroll")                                                     \
        for (int r = 0; r < 4; r++) {                                         \
            int idx = r * 256 + tid;     /* 0..1023 */                        \
            int row = idx >> 3, c8 = idx & 7;                                 \
            uint32_t so = (uint32_t)row * 128 +                               \
                          (((uint32_t)c8 * 16) ^ ((row & 7) << 4));           \
            size_t goA = (size_t)(m0 + row) * K + k0_ + c8 * 8;               \
            cp_async16(bo_ + oAh + so, Ah + goA);                             \
            cp_async16(bo_ + oAl + so, Al + goA);                             \
            size_t goB = (size_t)(n0 + row) * K + k0_ + c8 * 8;               \
            cp_async16(bo_ + oBh + so, Wh + goB);                             \
            cp_async16(bo_ + oBl + so, Wl + goB);                             \
        }                                                                     \
        asm volatile("cp.async.commit_group;" ::: "memory");                  \
    } while (0)

    PREFETCH2(0, 0);

    for (int s = 0; s < nstages; s++) {
        int buf = s & 1;
        if (s + 1 < nstages) {
            PREFETCH2(s + 1, buf ^ 1);
            asm volatile("cp.async.wait_group 1;" ::: "memory");
        } else {
            asm volatile("cp.async.wait_group 0;" ::: "memory");
        }
        __syncthreads();

        uint32_t bo = sb + buf * GBUF2;
#pragma unroll
        for (int kk = 0; kk < 4; kk++) {
            uint32_t cb = ((uint32_t)kk << 5) + qk;
            uint32_t ah[4][4], al[4][4], bh[2][4], bl[2][4];
#pragma unroll
            for (int mt = 0; mt < 4; mt++) {
                uint32_t ad = bo + oAh + aoff[mt] + (cb ^ asw[mt]);
                LDSM_X4(ah[mt][0], ah[mt][1], ah[mt][2], ah[mt][3], ad);
                LDSM_X4(al[mt][0], al[mt][1], al[mt][2], al[mt][3], ad + 16384);
            }
#pragma unroll
            for (int nt = 0; nt < 2; nt++) {
                uint32_t bd = bo + oBh + boff[nt] + (cb ^ bsw[nt]);
                LDSM_X4(bh[nt][0], bh[nt][1], bh[nt][2], bh[nt][3], bd);
                LDSM_X4(bl[nt][0], bl[nt][1], bl[nt][2], bl[nt][3], bd + 16384);
            }
#pragma unroll
            for (int mt = 0; mt < 4; mt++)
#pragma unroll
                for (int nt = 0; nt < 2; nt++)
#pragma unroll
                    for (int u = 0; u < 2; u++) {
                        int nf = nt * 2 + u;
                        MMA4(acc[mt][nf], ah[mt], bh[nt][u], bh[nt][u + 2]);
                        MMA4(acc[mt][nf], ah[mt], bl[nt][u], bl[nt][u + 2]);
                        MMA4(acc[mt][nf], al[mt], bh[nt][u], bh[nt][u + 2]);
                    }
        }
        __syncthreads();
    }
#undef PREFETCH2

#pragma unroll
    for (int mt = 0; mt < 4; mt++)
#pragma unroll
        for (int nf = 0; nf < 4; nf++) {
            int mrow = m0 + wm * 64 + mt * 16 + (lane >> 2);
            int ncol = n0 + wn * 32 + (nf >> 1) * 16 + (nf & 1) * 8 + 2 * (lane & 3);
            epi_write<EPI>(acc[mt][nf][0], mrow,     ncol,     N, bias, out, outh, outl, coLog2, ustr);
            epi_write<EPI>(acc[mt][nf][1], mrow,     ncol + 1, N, bias, out, outh, outl, coLog2, ustr);
            epi_write<EPI>(acc[mt][nf][2], mrow + 8, ncol,     N, bias, out, outh, outl, coLog2, ustr);
            epi_write<EPI>(acc[mt][nf][3], mrow + 8, ncol + 1, N, bias, out, outh, outl, coLog2, ustr);
        }
}

// ---------------------------------------------------------------------------
// 128x64-tile bf16 GEMM (L1-L3), double-buffered (R11 version).
// ---------------------------------------------------------------------------
#define GBUF 49152

template<int KC, int EPI>
__global__ __launch_bounds__(256)
void gemm_mmab(const __nv_bfloat16* __restrict__ Ah, const __nv_bfloat16* __restrict__ Al,
               const __nv_bfloat16* __restrict__ Wh, const __nv_bfloat16* __restrict__ Wl,
               const float* __restrict__ bias, float* __restrict__ out,
               __nv_bfloat16* __restrict__ outh, __nv_bfloat16* __restrict__ outl,
               int M, int N, int K, int coLog2, long long ustr) {
    extern __shared__ __align__(128) uint8_t smdyn[];
    const uint32_t sb = smem_u32(smdyn);
    const uint32_t oAh = 0, oAl = 16384, oBh = 32768, oBl = 40960;

    const int tid = threadIdx.x, lane = tid & 31, warp = tid >> 5;
    const int wm = warp & 3, wn = warp >> 2;
    const int m0 = blockIdx.y * 128, n0 = blockIdx.x * 64;

    float acc[2][4][4];
#pragma unroll
    for (int i = 0; i < 2; i++)
#pragma unroll
        for (int j = 0; j < 4; j++)
#pragma unroll
            for (int q = 0; q < 4; q++) acc[i][j][q] = 0.f;

    const uint32_t lq = lane >> 3, lr = lane & 7;
    const uint32_t qk = (lq >> 1) << 4;
    uint32_t aoff[2], asw[2], boff[2], bsw[2];
#pragma unroll
    for (int mt = 0; mt < 2; mt++) {
        int row = wm * 32 + mt * 16 + ((lq & 1) << 3) + lr;
        aoff[mt] = (uint32_t)row * 128;
        asw[mt] = (uint32_t)((row & 7) << 4);
    }
#pragma unroll
    for (int nt = 0; nt < 2; nt++) {
        int row = wn * 32 + nt * 16 + ((lq & 1) << 3) + lr;
        boff[nt] = (uint32_t)row * 128;
        bsw[nt] = (uint32_t)((row & 7) << 4);
    }

    constexpr int RPR = KC / 8;
    const int nstages = K / KC;

#define PREFETCH(S, BUF) do {                                                 \
        int k0_ = (S) * KC;                                                   \
        uint32_t bo_ = sb + (BUF) * GBUF;                                     \
        _Pragma("unroll")                                                     \
        for (int r = 0; r < KC / 16; r++) {                                   \
            int idx = r * 256 + tid;                                          \
            int row = idx / RPR, c8 = idx % RPR;                              \
            size_t go = (size_t)(m0 + row) * K + k0_ + c8 * 8;                \
            uint32_t so = (uint32_t)row * 128 +                               \
                          (((uint32_t)c8 * 16) ^ ((row & 7) << 4));           \
            cp_async16(bo_ + oAh + so, Ah + go);                              \
            cp_async16(bo_ + oAl + so, Al + go);                              \
        }                                                                     \
        _Pragma("unroll")                                                     \
        for (int r = 0; r < KC / 32; r++) {                                   \
            int idx = r * 256 + tid;                                          \
            int row = idx / RPR, c8 = idx % RPR;                              \
            size_t go = (size_t)(n0 + row) * K + k0_ + c8 * 8;                \
            uint32_t so = (uint32_t)row * 128 +                               \
                          (((uint32_t)c8 * 16) ^ ((row & 7) << 4));           \
            cp_async16(bo_ + oBh + so, Wh + go);                              \
            cp_async16(bo_ + oBl + so, Wl + go);                              \
        }                                                                     \
        asm volatile("cp.async.commit_group;" ::: "memory");                  \
    } while (0)

    PREFETCH(0, 0);

    for (int s = 0; s < nstages; s++) {
        int buf = s & 1;
        if (s + 1 < nstages) {
            PREFETCH(s + 1, buf ^ 1);
            asm volatile("cp.async.wait_group 1;" ::: "memory");
        } else {
            asm volatile("cp.async.wait_group 0;" ::: "memory");
        }
        __syncthreads();

        uint32_t bo = sb + buf * GBUF;
#pragma unroll
        for (int kk = 0; kk < KC / 16; kk++) {
            uint32_t cb = ((uint32_t)kk << 5) + qk;
            uint32_t ah[2][4], al[2][4], bh[2][4], bl[2][4];
#pragma unroll
            for (int mt = 0; mt < 2; mt++) {
                uint32_t ad = bo + oAh + aoff[mt] + (cb ^ asw[mt]);
                LDSM_X4(ah[mt][0], ah[mt][1], ah[mt][2], ah[mt][3], ad);
                LDSM_X4(al[mt][0], al[mt][1], al[mt][2], al[mt][3], ad + 16384);
            }
#pragma unroll
            for (int nt = 0; nt < 2; nt++) {
                uint32_t bd = bo + oBh + boff[nt] + (cb ^ bsw[nt]);
                LDSM_X4(bh[nt][0], bh[nt][1], bh[nt][2], bh[nt][3], bd);
                LDSM_X4(bl[nt][0], bl[nt][1], bl[nt][2], bl[nt][3], bd + 8192);
            }
#pragma unroll
            for (int mt = 0; mt < 2; mt++)
#pragma unroll
                for (int nt = 0; nt < 2; nt++)
#pragma unroll
                    for (int u = 0; u < 2; u++) {
                        int nf = nt * 2 + u;
                        MMA4(acc[mt][nf], ah[mt], bh[nt][u], bh[nt][u + 2]);
                        MMA4(acc[mt][nf], ah[mt], bl[nt][u], bl[nt][u + 2]);
                        MMA4(acc[mt][nf], al[mt], bh[nt][u], bh[nt][u + 2]);
                    }
        }
        __syncthreads();
    }
#undef PREFETCH

#pragma unroll
    for (int mt = 0; mt < 2; mt++)
#pragma unroll
        for (int nf = 0; nf < 4; nf++) {
            int mrow = m0 + wm * 32 + mt * 16 + (lane >> 2);
            int ncol = n0 + wn * 32 + (nf >> 1) * 16 + (nf & 1) * 8 + 2 * (lane & 3);
            epi_write<EPI>(acc[mt][nf][0], mrow,     ncol,     N, bias, out, outh, outl, coLog2, ustr);
            epi_write<EPI>(acc[mt][nf][1], mrow,     ncol + 1, N, bias, out, outh, outl, coLog2, ustr);
            epi_write<EPI>(acc[mt][nf][2], mrow + 8, ncol,     N, bias, out, outh, outl, coLog2, ustr);
            epi_write<EPI>(acc[mt][nf][3], mrow + 8, ncol + 1, N, bias, out, outh, outl, coLog2, ustr);
        }
}

// ---------------------------------------------------------------------------
// SIMT fp32 GEMM for FC1 (MODE 1) and L4 (MODE 3).
// ---------------------------------------------------------------------------
template<int BM, int BN, int TM, int TN, int MODE>
__global__ __launch_bounds__(256)
void gemm_k(const float* __restrict__ A, const float* __restrict__ W,
            const float* __restrict__ bias, float* __restrict__ out,
            int M, int N, int K, int co, long long ustr) {
    __shared__ float As[16][BM + 4];
    __shared__ float Ws[16][BN + 4];
    const int tid = threadIdx.x;
    const int tx = tid & 15, ty = tid >> 4;
    const int m0 = blockIdx.y * BM, n0 = blockIdx.x * BN;

    float acc[TM][TN];
#pragma unroll
    for (int i = 0; i < TM; i++)
#pragma unroll
        for (int j = 0; j < TN; j++) acc[i][j] = 0.0f;

    for (int k0 = 0; k0 < K; k0 += 16) {
#pragma unroll
        for (int r = 0; r < BM / 64; r++) {
            int lid = tid + r * 256;
            int row = lid >> 2;
            int kq = (lid & 3) << 2;
            float4 a = *(const float4*)(A + (size_t)(m0 + row) * K + (k0 + kq));
            As[kq + 0][row] = a.x;
            As[kq + 1][row] = a.y;
            As[kq + 2][row] = a.z;
            As[kq + 3][row] = a.w;
        }
#pragma unroll
        for (int r = 0; r < BN / 64; r++) {
            int lid = tid + r * 256;
            int k = lid / (BN / 4);
            int n4 = (lid % (BN / 4)) * 4;
            int gc = n0 + n4;
            float4 w;
            if (((N & 3) == 0) && gc + 4 <= N) {
                w = *(const float4*)(W + (size_t)(k0 + k) * N + gc);
            } else {
                w.x = (gc + 0 < N) ? W[(size_t)(k0 + k) * N + gc + 0] : 0.f;
                w.y = (gc + 1 < N) ? W[(size_t)(k0 + k) * N + gc + 1] : 0.f;
                w.z = (gc + 2 < N) ? W[(size_t)(k0 + k) * N + gc + 2] : 0.f;
                w.w = (gc + 3 < N) ? W[(size_t)(k0 + k) * N + gc + 3] : 0.f;
            }
            *(float4*)&Ws[k][n4] = w;
        }
        __syncthreads();

#pragma unroll
        for (int k = 0; k < 16; k++) {
            float a[TM], w[TN];
#pragma unroll
            for (int i = 0; i < TM / 4; i++)
                *(float4*)&a[4 * i] = *(const float4*)&As[k][ty * TM + 4 * i];
#pragma unroll
            for (int j = 0; j < TN / 4; j++)
                *(float4*)&w[4 * j] = *(const float4*)&Ws[k][tx * TN + 4 * j];
#pragma unroll
            for (int i = 0; i < TM; i++)
#pragma unroll
                for (int j = 0; j < TN; j++) acc[i][j] += a[i] * w[j];
        }
        __syncthreads();
    }

#pragma unroll
    for (int i = 0; i < TM; i++) {
        int m = m0 + ty * TM + i;
#pragma unroll
        for (int j = 0; j < TN; j++) {
            int n = n0 + tx * TN + j;
            if (n >= N) continue;
            float v = acc[i][j];
            if (MODE == 1) {
                v += bias[n];
                v = v > 0.f ? v : 0.f;
                out[(size_t)m * N + n] = v;
            } else {
                int t = n / co;
                out[(size_t)t * (size_t)ustr + (size_t)m * co + (n - t * co)] = v;
            }
        }
    }
}

// ---------------------------------------------------------------------------
// Props (CSR slice selected by nb):
//   Y[v] = U1[v>>shU] + 2 * sum_e w * U2[src>>shU]
//   out[v] = act( U0[v>>shU] + sum_e w * Y[src] + bias )
// ---------------------------------------------------------------------------
__global__ void propY_kernel(float4* __restrict__ Y, const float4* __restrict__ U1,
                             const float4* __restrict__ U2, int R4, int shU, int nb) {
    int v = blockIdx.y;
    int j = blockIdx.x * blockDim.x + threadIdx.x;
    float4 acc = make_float4(0.f, 0.f, 0.f, 0.f);
    int s = g_off[nb + v], t = g_off[nb + v + 1];
    for (int q = s; q < t; q++) {
        float w = g_cw[q];
        float4 x = U2[(size_t)(g_csrc[q] >> shU) * R4 + j];
        acc.x += w * x.x; acc.y += w * x.y; acc.z += w * x.z; acc.w += w * x.w;
    }
    float4 u1 = U1[(size_t)(v >> shU) * R4 + j];
    acc.x = u1.x + 2.f * acc.x;
    acc.y = u1.y + 2.f * acc.y;
    acc.z = u1.z + 2.f * acc.z;
    acc.w = u1.w + 2.f * acc.w;
    Y[(size_t)v * R4 + j] = acc;
}

// OUTF: 0 -> fp32 out; 1 -> bf16 hi/lo split (feeds next mma GEMM)
template<int OUTF>
__global__ void propF_kernel(float* __restrict__ outf,
                             __nv_bfloat16* __restrict__ outh,
                             __nv_bfloat16* __restrict__ outl,
                             const float4* __restrict__ U0, const float4* __restrict__ Y,
                             const float* __restrict__ bias, int R4, int comask,
                             int shU, int nb) {
    int v = blockIdx.y;
    int j = blockIdx.x * blockDim.x + threadIdx.x;
    float4 acc = U0[(size_t)(v >> shU) * R4 + j];
    int s = g_off[nb + v], t = g_off[nb + v + 1];
    for (int q = s; q < t; q++) {
        float w = g_cw[q];
        float4 y = Y[(size_t)g_csrc[q] * R4 + j];
        acc.x += w * y.x; acc.y += w * y.y; acc.z += w * y.z; acc.w += w * y.w;
    }
    int c0 = (4 * j) & comask;
    float4 bb = *(const float4*)&bias[c0];
    acc.x += bb.x; acc.y += bb.y; acc.z += bb.z; acc.w += bb.w;
    acc.x = acc.x >= 0.f ? acc.x : LRELU_S * acc.x;
    acc.y = acc.y >= 0.f ? acc.y : LRELU_S * acc.y;
    acc.z = acc.z >= 0.f ? acc.z : LRELU_S * acc.z;
    acc.w = acc.w >= 0.f ? acc.w : LRELU_S * acc.w;
    if (OUTF == 0) {
        ((float4*)outf)[(size_t)v * R4 + j] = acc;
    } else {
        size_t o = (size_t)v * R4 * 4 + 4 * j;
        __nv_bfloat16 h[4], l[4];
        float vv[4] = {acc.x, acc.y, acc.z, acc.w};
#pragma unroll
        for (int e = 0; e < 4; e++) {
            h[e] = __float2bfloat16(vv[e]);
            l[e] = __float2bfloat16(vv[e] - __bfloat162float(h[e]));
        }
        *(uint2*)(outh + o) = *(uint2*)h;
        *(uint2*)(outl + o) = *(uint2*)l;
    }
}

__global__ void propF3_kernel(float* __restrict__ out, const float* __restrict__ U0,
                              const float* __restrict__ Y,
                              const float* __restrict__ bias, int nb) {
    int v = blockIdx.y;
    int p = blockIdx.x * blockDim.x + threadIdx.x;   // < 384
    float acc = U0[(size_t)v * 384 + p];
    int s = g_off[nb + v], t = g_off[nb + v + 1];
    for (int q = s; q < t; q++)
        acc += g_cw[q] * Y[(size_t)g_csrc[q] * 384 + p];
    out[(size_t)v * 384 + p] = acc + bias[p % 3];
}

__global__ void final_kernel(float* __restrict__ out, const float* __restrict__ h,
                             const void* __restrict__ perm) {
    int i = blockIdx.x * blockDim.x + threadIdx.x;
    const int TOT = 128 * 6890 * 3;
    if (i < TOT) {
        int b = i / (6890 * 3);
        int r = i - b * (6890 * 3);
        int u = r / 3;
        int k = r - u * 3;
        int v = read_idx(perm, u);
        out[i] = h[(size_t)(v * 128 + b) * 3 + k];
    }
}

// ---------------------------------------------------------------------------
extern "C" void kernel_launch(void* const* d_in, const int* in_sizes, int n_in,
                              void* d_out, int out_size) {
    const float* x   = (const float*)d_in[0];
    const float* fw1 = (const float*)d_in[1];
    const float* fb1 = (const float*)d_in[2];
    const float* fw2 = (const float*)d_in[3];
    const float* fb2 = (const float*)d_in[4];
    const float* W[5];
    const float* bb[5];
    for (int i = 0; i < 5; i++) {
        W[i]  = (const float*)d_in[5 + 2 * i];
        bb[i] = (const float*)d_in[6 + 2 * i];
    }
    const void* edges[4];
    for (int i = 0; i < 4; i++) edges[i] = d_in[15 + i];
    const void* perm = d_in[19];
    float* out = (float*)d_out;

    float *T, *OA, *YB, *H1, *WC;
    __nv_bfloat16 *AH, *AL, *WTH, *WTL, *W2H, *W2L, *H1H, *H1L;
    cudaGetSymbolAddress((void**)&T,   g_T);
    cudaGetSymbolAddress((void**)&OA,  g_outA);
    cudaGetSymbolAddress((void**)&YB,  g_Y);
    cudaGetSymbolAddress((void**)&H1,  g_h1);
    cudaGetSymbolAddress((void**)&WC,  g_wc);
    cudaGetSymbolAddress((void**)&AH,  g_Ah);
    cudaGetSymbolAddress((void**)&AL,  g_Al);
    cudaGetSymbolAddress((void**)&WTH, g_wth);
    cudaGetSymbolAddress((void**)&WTL, g_wtl);
    cudaGetSymbolAddress((void**)&W2H, g_w2h);
    cudaGetSymbolAddress((void**)&W2L, g_w2l);
    cudaGetSymbolAddress((void**)&H1H, g_h1h);
    cudaGetSymbolAddress((void**)&H1L, g_h1l);

    const int DSM  = 2 * GBUF;    // 96KB (BN=64 kernel)
    const int DSM2 = 2 * GBUF2;   // 128KB (BN=128 kernel)
    cudaFuncSetAttribute(gemm_mmab<64, 0>,
                         cudaFuncAttributeMaxDynamicSharedMemorySize, DSM);
    cudaFuncSetAttribute(gemm_mmab<32, 0>,
                         cudaFuncAttributeMaxDynamicSharedMemorySize, DSM);
    cudaFuncSetAttribute(gemm_mmab128<0>,
                         cudaFuncAttributeMaxDynamicSharedMemorySize, DSM2);
    cudaFuncSetAttribute(gemm_mmab128<1>,
                         cudaFuncAttributeMaxDynamicSharedMemorySize, DSM2);

    const int ns[5]   = {864, 1728, 3456, 6912, 6912};
    const int cis[5]  = {128, 128, 64, 32, 16};
    const int cos_[5] = {128, 64, 32, 16, 3};
    const int col2[5] = {7, 6, 5, 4, 0};
    const int nbArr[5] = {0, 864, 2592, 6048, 6048};

    // 0: FC1 (SIMT)
    gemm_k<128, 128, 8, 8, 1><<<dim3(4, 1), 256>>>(x, fw1, fb1, H1,
                                                   128, 512, 128, 0, 0);
    // 1: split FC1 output
    hsplit_kernel<<<256, 256>>>(H1, H1H, H1L);
    // 2: transpose+split fc_w2 -> (N x K) bf16 hi/lo
    tsplit_kernel<<<dim3(110592 / 32, 512 / 32), dim3(32, 8)>>>(fw2, W2H, W2L);
    // 3: FC2 GEMM (128x128 tile) — ncu capture target
    gemm_mmab128<1><<<dim3(110592 / 128, 1), 256, DSM2>>>(
        H1H, H1L, W2H, W2L, fb2, nullptr, AH, AL, 128, 110592, 512, 0, 0);
    // 4: combined weights for layer 0
    wprep_kernel<<<(384 * 128 + 255) / 256, 256>>>(W[0], WC, WTH, WTL, 128, 128, 384);
    // 5: layer-0 ChebConv GEMM (128x128 tile)
    gemm_mmab128<0><<<dim3(3, 864), 256, DSM2>>>(AH, AL, WTH, WTL, nullptr, T,
                                                 nullptr, nullptr,
                                                 110592, 384, 128, 7, 14155776LL);
    // 6: dtype sniff, then fused CSR build for all 4 graphs
    detect_kernel<<<1, 256>>>((const int*)edges[0], 5184);
    csr_zero_kernel<<<(12960 + 255) / 256, 256>>>();
    csr_count_kernel<<<dim3(162, 4), 256>>>(edges[0], edges[1], edges[2], edges[3]);
    csr_dinv_kernel<<<(12960 + 255) / 256, 256>>>();
    csr_scan_kernel<<<4, 1024>>>();
    csr_fill_kernel<<<dim3(162, 4), 256>>>(edges[0], edges[1], edges[2], edges[3]);

    for (int l = 0; l < 5; l++) {
        int n  = ns[l];
        int ci = cis[l];
        int co = cos_[l];
        int N  = 3 * co;
        int Np = ((N + 63) / 64) * 64;
        int ng = (l == 0 || l == 4) ? n : n / 2;   // layers 1-3 un-repeated
        int Mg = ng * 128;
        int shU = (l == 0 || l == 4) ? 0 : 1;
        int R4 = 32 * co;
        long long US = (long long)Mg * co;
        int nb = nbArr[l];

        if (l > 0) {
            wprep_kernel<<<(Np * ci + 255) / 256, 256>>>(W[l], WC, WTH, WTL,
                                                         ci, co, Np);
            if (l < 4) {   // mma path (128x64 tile)
                if (ci % 64 == 0)
                    gemm_mmab<64, 0><<<dim3(Np / 64, Mg / 128), 256, DSM>>>(
                        AH, AL, WTH, WTL, nullptr, T, nullptr, nullptr,
                        Mg, N, ci, col2[l], US);
                else
                    gemm_mmab<32, 0><<<dim3(Np / 64, Mg / 128), 256, DSM>>>(
                        AH, AL, WTH, WTL, nullptr, T, nullptr, nullptr,
                        Mg, N, ci, col2[l], US);
            } else {       // L4: K=16, SIMT
                gemm_k<256, 64, 16, 4, 3><<<dim3(1, Mg / 256), 256>>>(
                    OA, WC, nullptr, T, Mg, N, ci, co, US);
            }
        }

        // Y = U1' + 2*P*U2'
        propY_kernel<<<dim3(R4 >= 256 ? R4 / 256 : 1, n), R4 < 256 ? R4 : 256>>>(
            (float4*)YB, (const float4*)(T + US), (const float4*)(T + 2 * US),
            R4, shU, nb);
        // out = act(U0' + P*Y + b)
        if (l < 3) {
            propF_kernel<1><<<dim3(R4 / 256, n), 256>>>(
                nullptr, AH, AL, (const float4*)T, (const float4*)YB,
                bb[l], R4, co - 1, shU, nb);
        } else if (l == 3) {
            propF_kernel<0><<<dim3(R4 / 256, n), 256>>>(
                OA, nullptr, nullptr, (const float4*)T, (const float4*)YB,
                bb[l], R4, co - 1, shU, nb);
        } else {
            propF3_kernel<<<dim3(3, n), 128>>>(OA, T, YB, bb[4], nb);
        }
    }

    const int TOT = 128 * 6890 * 3;
    final_kernel<<<(TOT + 255) / 256, 256>>>(out, OA, perm);
}

// round 14
// speedup vs baseline: 1.1071x; 1.1071x over previous
#include <cuda_runtime.h>
#include <cuda_bf16.h>
#include <cstdint>

// ---------------------------------------------------------------------------
// ChebGcnDecoder, commuted form. GEMMs on mma.sync bf16 hi/lo 3-split with
// pre-split bf16 inputs, cp.async double-buffered smem (128x64 tile — the
// measured optimum). R14: FC2 loads its fp32 weights directly (in-kernel
// B split, latency-hidden), eliminating the 452MB tsplit pass.
// ---------------------------------------------------------------------------

#define LRELU_S 0.2f

__device__ float g_T[42467328];            // U0|U1|U2, stride Mg*co
__device__ float g_outA[14155776];         // fp32 layer output (l=3)
__device__ float g_Y[14155776];            // Y = U1 + 2*P*U2
__device__ __nv_bfloat16 g_Ah[14155776];   // bf16-hi GEMM input (activations)
__device__ __nv_bfloat16 g_Al[14155776];   // bf16-lo
__device__ float g_h1[65536];              // FC1 output 128x512 fp32
__device__ __nv_bfloat16 g_h1h[65536];
__device__ __nv_bfloat16 g_h1l[65536];
__device__ float g_wc[49152];              // combined weights fp32 (K x N), L4
__device__ __nv_bfloat16 g_wth[49152];     // combined weights bf16-hi (Np x K)
__device__ __nv_bfloat16 g_wtl[49152];
__device__ int   g_cnt[12960];
__device__ float g_dinv[12960];
__device__ int   g_off[12961];
__device__ int   g_cur[12960];
__device__ int   g_csrc[77760];
__device__ float g_cw[77760];
__device__ int   g_is64;

__constant__ int c_nb[4] = {0, 864, 2592, 6048};
__constant__ int c_eb[4] = {0, 5184, 15552, 36288};
__constant__ int c_nl[4] = {864, 1728, 3456, 6912};

// ---------------------------------------------------------------------------
__device__ __forceinline__ int read_idx(const void* p, int i) {
    if (g_is64) return (int)((const long long*)p)[i];
    return ((const int*)p)[i];
}

__global__ void detect_kernel(const int* w, int nwords) {
    __shared__ int any;
    if (threadIdx.x == 0) any = 0;
    __syncthreads();
    int a = 0;
    for (int i = 1 + 2 * (int)threadIdx.x; i < nwords; i += 2 * blockDim.x) a |= w[i];
    if (a) atomicOr(&any, 1);
    __syncthreads();
    if (threadIdx.x == 0) g_is64 = any ? 0 : 1;
}

// ---- fused CSR build over all 4 graphs ----
__global__ void csr_zero_kernel() {
    int i = blockIdx.x * blockDim.x + threadIdx.x;
    if (i < 12960) g_cnt[i] = 0;
}

__global__ void csr_count_kernel(const void* e0, const void* e1,
                                 const void* e2, const void* e3) {
    int l = blockIdx.y;
    const void* eg = (l == 0) ? e0 : (l == 1) ? e1 : (l == 2) ? e2 : e3;
    int e = 6 * c_nl[l];
    int i = blockIdx.x * blockDim.x + threadIdx.x;
    if (i < e) atomicAdd(&g_cnt[c_nb[l] + read_idx(eg, e + i)], 1);
}

__global__ void csr_dinv_kernel() {
    int i = blockIdx.x * blockDim.x + threadIdx.x;
    if (i < 12960) g_dinv[i] = (g_cnt[i] > 0) ? rsqrtf((float)g_cnt[i]) : 0.0f;
}

__global__ void csr_scan_kernel() {
    __shared__ int partial[1024];
    int l = blockIdx.x;
    int n = c_nl[l], nb = c_nb[l], eb = c_eb[l];
    int tid = threadIdx.x;
    int C = (n + 1023) / 1024;
    int start = tid * C;
    int local[8];
    int s = 0;
    for (int i = 0; i < C; i++) {
        int idx = start + i;
        int v = (idx < n) ? g_cnt[nb + idx] : 0;
        local[i] = s;
        s += v;
    }
    partial[tid] = s;
    __syncthreads();
    for (int d = 1; d < 1024; d <<= 1) {
        int t = (tid >= d) ? partial[tid - d] : 0;
        __syncthreads();
        if (tid >= d) partial[tid] += t;
        __syncthreads();
    }
    int base = (tid > 0) ? partial[tid - 1] : 0;
    for (int i = 0; i < C; i++) {
        int idx = start + i;
        if (idx < n) {
            int o = eb + base + local[i];
            g_off[nb + idx] = o;
            g_cur[nb + idx] = o;
        }
    }
    if (l == 3 && tid == 1023) g_off[12960] = 77760;
}

__global__ void csr_fill_kernel(const void* e0, const void* e1,
                                const void* e2, const void* e3) {
    int l = blockIdx.y;
    const void* eg = (l == 0) ? e0 : (l == 1) ? e1 : (l == 2) ? e2 : e3;
    int e = 6 * c_nl[l];
    int nb = c_nb[l];
    int i = blockIdx.x * blockDim.x + threadIdx.x;
    if (i < e) {
        int s = read_idx(eg, i);
        int d = read_idx(eg, e + i);
        int p = atomicAdd(&g_cur[nb + d], 1);
        g_csrc[p] = s;
        g_cw[p] = -g_dinv[nb + s] * g_dinv[nb + d];
    }
}

// Combined weights [W0-W2 | W1 | W2]: fp32 (K x N) for SIMT L4, bf16 hi/lo
// transposed (Np x K) for the mma path. Factor 2 on P^2 applied in props.
__global__ void wprep_kernel(const float* __restrict__ W,
                             float* __restrict__ Wc,
                             __nv_bfloat16* __restrict__ Wth,
                             __nv_bfloat16* __restrict__ Wtl,
                             int ci, int co, int Np) {
    int i = blockIdx.x * blockDim.x + threadIdx.x;
    int N = 3 * co;
    if (i >= Np * ci) return;
    int n = i / ci, k = i - n * ci;
    int cico = ci * co;
    float v = 0.f;
    if (n < N) {
        if (n < co)            v = W[k * co + n] - W[2 * cico + k * co + n];
        else if (n < 2 * co)   v = W[cico + k * co + (n - co)];
        else                   v = W[2 * cico + k * co + (n - 2 * co)];
        Wc[k * N + n] = v;
    }
    __nv_bfloat16 h = __float2bfloat16(v);
    Wth[n * ci + k] = h;
    Wtl[n * ci + k] = __float2bfloat16(v - __bfloat162float(h));
}

// split FC1 output (128x512) into bf16 hi/lo
__global__ void hsplit_kernel(const float* __restrict__ in,
                              __nv_bfloat16* __restrict__ outh,
                              __nv_bfloat16* __restrict__ outl) {
    int i = blockIdx.x * blockDim.x + threadIdx.x;
    if (i < 65536) {
        float v = in[i];
        __nv_bfloat16 h = __float2bfloat16(v);
        outh[i] = h;
        outl[i] = __float2bfloat16(v - __bfloat162float(h));
    }
}

// ---------------------------------------------------------------------------
__device__ __forceinline__ uint32_t smem_u32(const void* p) {
    uint32_t a;
    asm("{ .reg .u64 t; cvta.to.shared.u64 t, %1; cvt.u32.u64 %0, t; }"
        : "=r"(a) : "l"(p));
    return a;
}

__device__ __forceinline__ void cp_async16(uint32_t dst, const void* src) {
    asm volatile("cp.async.cg.shared.global [%0], [%1], 16;"
                 :: "r"(dst), "l"(src));
}

#define LDSM_X4(r0, r1, r2, r3, a)                                            \
    asm volatile("ldmatrix.sync.aligned.m8n8.x4.shared.b16 {%0,%1,%2,%3}, [%4];" \
        : "=r"(r0), "=r"(r1), "=r"(r2), "=r"(r3) : "r"(a))

#define MMA4(c, a, b0, b1)                                                    \
    asm volatile(                                                             \
        "mma.sync.aligned.m16n8k16.row.col.f32.bf16.bf16.f32 "                \
        "{%0,%1,%2,%3}, {%4,%5,%6,%7}, {%8,%9}, {%0,%1,%2,%3};\n"             \
        : "+f"((c)[0]), "+f"((c)[1]), "+f"((c)[2]), "+f"((c)[3])              \
        : "r"((a)[0]), "r"((a)[1]), "r"((a)[2]), "r"((a)[3]),                 \
          "r"(b0), "r"(b1))

// ---------------------------------------------------------------------------
// 128x64-tile bf16 GEMM for the layer GEMMs (proven R11/R12 config).
// C(MxN) = A(MxK)@Wt^T, all inputs pre-split hi/lo. Wt is (Np x K) row-major.
// Epilogue: split write into U0|U1|U2 (t = n>>coLog2) at out + t*ustr (fp32).
// ---------------------------------------------------------------------------
#define GBUF 49152

template<int KC>
__global__ __launch_bounds__(256)
void gemm_mmab(const __nv_bfloat16* __restrict__ Ah, const __nv_bfloat16* __restrict__ Al,
               const __nv_bfloat16* __restrict__ Wh, const __nv_bfloat16* __restrict__ Wl,
               float* __restrict__ out,
               int M, int N, int K, int coLog2, long long ustr) {
    extern __shared__ __align__(128) uint8_t smdyn[];
    const uint32_t sb = smem_u32(smdyn);
    const uint32_t oAh = 0, oAl = 16384, oBh = 32768, oBl = 40960;

    const int tid = threadIdx.x, lane = tid & 31, warp = tid >> 5;
    const int wm = warp & 3, wn = warp >> 2;
    const int m0 = blockIdx.y * 128, n0 = blockIdx.x * 64;

    float acc[2][4][4];
#pragma unroll
    for (int i = 0; i < 2; i++)
#pragma unroll
        for (int j = 0; j < 4; j++)
#pragma unroll
            for (int q = 0; q < 4; q++) acc[i][j][q] = 0.f;

    const uint32_t lq = lane >> 3, lr = lane & 7;
    const uint32_t qk = (lq >> 1) << 4;
    uint32_t aoff[2], asw[2], boff[2], bsw[2];
#pragma unroll
    for (int mt = 0; mt < 2; mt++) {
        int row = wm * 32 + mt * 16 + ((lq & 1) << 3) + lr;
        aoff[mt] = (uint32_t)row * 128;
        asw[mt] = (uint32_t)((row & 7) << 4);
    }
#pragma unroll
    for (int nt = 0; nt < 2; nt++) {
        int row = wn * 32 + nt * 16 + ((lq & 1) << 3) + lr;
        boff[nt] = (uint32_t)row * 128;
        bsw[nt] = (uint32_t)((row & 7) << 4);
    }

    constexpr int RPR = KC / 8;
    const int nstages = K / KC;

#define PREFETCH(S, BUF) do {                                                 \
        int k0_ = (S) * KC;                                                   \
        uint32_t bo_ = sb + (BUF) * GBUF;                                     \
        _Pragma("unroll")                                                     \
        for (int r = 0; r < KC / 16; r++) {                                   \
            int idx = r * 256 + tid;                                          \
            int row = idx / RPR, c8 = idx % RPR;                              \
            size_t go = (size_t)(m0 + row) * K + k0_ + c8 * 8;                \
            uint32_t so = (uint32_t)row * 128 +                               \
                          (((uint32_t)c8 * 16) ^ ((row & 7) << 4));           \
            cp_async16(bo_ + oAh + so, Ah + go);                              \
            cp_async16(bo_ + oAl + so, Al + go);                              \
        }                                                                     \
        _Pragma("unroll")                                                     \
        for (int r = 0; r < KC / 32; r++) {                                   \
            int idx = r * 256 + tid;                                          \
            int row = idx / RPR, c8 = idx % RPR;                              \
            size_t go = (size_t)(n0 + row) * K + k0_ + c8 * 8;                \
            uint32_t so = (uint32_t)row * 128 +                               \
                          (((uint32_t)c8 * 16) ^ ((row & 7) << 4));           \
            cp_async16(bo_ + oBh + so, Wh + go);                              \
            cp_async16(bo_ + oBl + so, Wl + go);                              \
        }                                                                     \
        asm volatile("cp.async.commit_group;" ::: "memory");                  \
    } while (0)

    PREFETCH(0, 0);

    for (int s = 0; s < nstages; s++) {
        int buf = s & 1;
        if (s + 1 < nstages) {
            PREFETCH(s + 1, buf ^ 1);
            asm volatile("cp.async.wait_group 1;" ::: "memory");
        } else {
            asm volatile("cp.async.wait_group 0;" ::: "memory");
        }
        __syncthreads();

        uint32_t bo = sb + buf * GBUF;
#pragma unroll
        for (int kk = 0; kk < KC / 16; kk++) {
            uint32_t cb = ((uint32_t)kk << 5) + qk;
            uint32_t ah[2][4], al[2][4], bh[2][4], bl[2][4];
#pragma unroll
            for (int mt = 0; mt < 2; mt++) {
                uint32_t ad = bo + oAh + aoff[mt] + (cb ^ asw[mt]);
                LDSM_X4(ah[mt][0], ah[mt][1], ah[mt][2], ah[mt][3], ad);
                LDSM_X4(al[mt][0], al[mt][1], al[mt][2], al[mt][3], ad + 16384);
            }
#pragma unroll
            for (int nt = 0; nt < 2; nt++) {
                uint32_t bd = bo + oBh + boff[nt] + (cb ^ bsw[nt]);
                LDSM_X4(bh[nt][0], bh[nt][1], bh[nt][2], bh[nt][3], bd);
                LDSM_X4(bl[nt][0], bl[nt][1], bl[nt][2], bl[nt][3], bd + 8192);
            }
#pragma unroll
            for (int mt = 0; mt < 2; mt++)
#pragma unroll
                for (int nt = 0; nt < 2; nt++)
#pragma unroll
                    for (int u = 0; u < 2; u++) {
                        int nf = nt * 2 + u;
                        MMA4(acc[mt][nf], ah[mt], bh[nt][u], bh[nt][u + 2]);
                        MMA4(acc[mt][nf], ah[mt], bl[nt][u], bl[nt][u + 2]);
                        MMA4(acc[mt][nf], al[mt], bh[nt][u], bh[nt][u + 2]);
                    }
        }
        __syncthreads();
    }
#undef PREFETCH

#pragma unroll
    for (int mt = 0; mt < 2; mt++)
#pragma unroll
        for (int nf = 0; nf < 4; nf++) {
            int mrow = m0 + wm * 32 + mt * 16 + (lane >> 2);
            int ncol = n0 + wn * 32 + (nf >> 1) * 16 + (nf & 1) * 8 + 2 * (lane & 3);
#pragma unroll
            for (int e = 0; e < 4; e++) {
                int m = mrow + (e >> 1) * 8;
                int n = ncol + (e & 1);
                if (n >= N) continue;
                int t = n >> coLog2;
                int cc = n & ((1 << coLog2) - 1);
                out[(size_t)t * (size_t)ustr + ((size_t)m << coLog2) + cc] =
                    acc[mt][nf][e];
            }
        }
}

// ---------------------------------------------------------------------------
// FC2 GEMM: A pre-split bf16 (128 x 512), B loaded DIRECTLY from fp32 fc_w2
// (K-major, K=512 x N=110592) with in-kernel hi/lo split. B LDGs issue at
// stage top (latency hidden under MMAs); convert+STS into the next buffer
// after the compute loop. Epilogue: bias + bf16 split to (node,batch,ch).
// ---------------------------------------------------------------------------
__global__ __launch_bounds__(256)
void gemm_fc2d(const __nv_bfloat16* __restrict__ Ah, const __nv_bfloat16* __restrict__ Al,
               const float* __restrict__ W, const float* __restrict__ bias,
               __nv_bfloat16* __restrict__ outh, __nv_bfloat16* __restrict__ outl,
               int M, int N, int K) {
    extern __shared__ __align__(128) uint8_t smdyn[];
    const uint32_t sb = smem_u32(smdyn);
    const uint32_t oAh = 0, oAl = 16384, oBh = 32768, oBl = 40960;

    const int tid = threadIdx.x, lane = tid & 31, warp = tid >> 5;
    const int wm = warp & 3, wn = warp >> 2;
    const int m0 = blockIdx.y * 128, n0 = blockIdx.x * 64;

    float acc[2][4][4];
#pragma unroll
    for (int i = 0; i < 2; i++)
#pragma unroll
        for (int j = 0; j < 4; j++)
#pragma unroll
            for (int q = 0; q < 4; q++) acc[i][j][q] = 0.f;

    const uint32_t lq = lane >> 3, lr = lane & 7;
    const uint32_t qk = (lq >> 1) << 4;
    uint32_t aoff[2], asw[2], boff[2], bsw[2];
#pragma unroll
    for (int mt = 0; mt < 2; mt++) {
        int row = wm * 32 + mt * 16 + ((lq & 1) << 3) + lr;
        aoff[mt] = (uint32_t)row * 128;
        asw[mt] = (uint32_t)((row & 7) << 4);
    }
#pragma unroll
    for (int nt = 0; nt < 2; nt++) {
        int row = wn * 32 + nt * 16 + ((lq & 1) << 3) + lr;
        boff[nt] = (uint32_t)row * 128;
        bsw[nt] = (uint32_t)((row & 7) << 4);
    }

    // B lane mapping (fixed): this thread handles 8 (kp, nn) pairs per stage
    const int kp0 = tid >> 6;            // base k-pair, step 4 per r
    const int nn  = tid & 63;
    const int gn  = n0 + nn;
    const uint32_t bso = (uint32_t)nn * 128;
    const uint32_t bsw2 = (uint32_t)((nn & 7) << 4);

    const int nstages = K >> 6;          // KC = 64

    // A prefetch (cp.async) for stage S into buffer BUF
#define PREFA(S, BUF) do {                                                    \
        int k0_ = (S) << 6;                                                   \
        uint32_t bo_ = sb + (BUF) * GBUF;                                     \
        _Pragma("unroll")                                                     \
        for (int r = 0; r < 4; r++) {                                         \
            int idx = r * 256 + tid;                                          \
            int row = idx >> 3, c8 = idx & 7;                                 \
            size_t go = (size_t)(m0 + row) * K + k0_ + c8 * 8;                \
            uint32_t so = (uint32_t)row * 128 +                               \
                          (((uint32_t)c8 * 16) ^ ((row & 7) << 4));           \
            cp_async16(bo_ + oAh + so, Ah + go);                              \
            cp_async16(bo_ + oAl + so, Al + go);                              \
        }                                                                     \
        asm volatile("cp.async.commit_group;" ::: "memory");                  \
    } while (0)

    // B LDG for stage S (16 fp32 into wreg)
#define LOADB(S, wreg) do {                                                   \
        int k0_ = (S) << 6;                                                   \
        _Pragma("unroll")                                                     \
        for (int r = 0; r < 8; r++) {                                         \
            int kp = kp0 + r * 4;                                             \
            (wreg)[2 * r]     = W[(size_t)(k0_ + 2 * kp) * N + gn];           \
            (wreg)[2 * r + 1] = W[(size_t)(k0_ + 2 * kp + 1) * N + gn];       \
        }                                                                     \
    } while (0)

    // convert wreg -> bf16 hi/lo, store into buffer BUF
#define STOREB(wreg, BUF) do {                                                \
        uint32_t bo_ = sb + (BUF) * GBUF;                                     \
        _Pragma("unroll")                                                     \
        for (int r = 0; r < 8; r++) {                                         \
            int kp = kp0 + r * 4;                                             \
            float w0 = (wreg)[2 * r], w1 = (wreg)[2 * r + 1];                 \
            __nv_bfloat162 h, l;                                              \
            h.x = __float2bfloat16(w0);                                       \
            l.x = __float2bfloat16(w0 - __bfloat162float(h.x));               \
            h.y = __float2bfloat16(w1);                                       \
            l.y = __float2bfloat16(w1 - __bfloat162float(h.y));               \
            uint32_t o = bso + (((uint32_t)(4 * kp)) ^ bsw2);                 \
            *(__nv_bfloat162*)(smdyn + (bo_ - sb) + oBh + o) = h;             \
            *(__nv_bfloat162*)(smdyn + (bo_ - sb) + oBl + o) = l;             \
        }                                                                     \
    } while (0)

    float wcur[16];
    // preamble: stage 0 A + B
    PREFA(0, 0);
    LOADB(0, wcur);
    STOREB(wcur, 0);

    for (int s = 0; s < nstages; s++) {
        int buf = s & 1;
        float wnext[16];
        if (s + 1 < nstages) {
            PREFA(s + 1, buf ^ 1);
            LOADB(s + 1, wnext);           // LDG latency hides under MMAs below
            asm volatile("cp.async.wait_group 1;" ::: "memory");
        } else {
            asm volatile("cp.async.wait_group 0;" ::: "memory");
        }
        __syncthreads();

        uint32_t bo = sb + buf * GBUF;
#pragma unroll
        for (int kk = 0; kk < 4; kk++) {
            uint32_t cb = ((uint32_t)kk << 5) + qk;
            uint32_t ah[2][4], al[2][4], bh[2][4], bl[2][4];
#pragma unroll
            for (int mt = 0; mt < 2; mt++) {
                uint32_t ad = bo + oAh + aoff[mt] + (cb ^ asw[mt]);
                LDSM_X4(ah[mt][0], ah[mt][1], ah[mt][2], ah[mt][3], ad);
                LDSM_X4(al[mt][0], al[mt][1], al[mt][2], al[mt][3], ad + 16384);
            }
#pragma unroll
            for (int nt = 0; nt < 2; nt++) {
                uint32_t bd = bo + oBh + boff[nt] + (cb ^ bsw[nt]);
                LDSM_X4(bh[nt][0], bh[nt][1], bh[nt][2], bh[nt][3], bd);
                LDSM_X4(bl[nt][0], bl[nt][1], bl[nt][2], bl[nt][3], bd + 8192);
            }
#pragma unroll
            for (int mt = 0; mt < 2; mt++)
#pragma unroll
                for (int nt = 0; nt < 2; nt++)
#pragma unroll
                    for (int u = 0; u < 2; u++) {
                        int nf = nt * 2 + u;
                        MMA4(acc[mt][nf], ah[mt], bh[nt][u], bh[nt][u + 2]);
                        MMA4(acc[mt][nf], ah[mt], bl[nt][u], bl[nt][u + 2]);
                        MMA4(acc[mt][nf], al[mt], bh[nt][u], bh[nt][u + 2]);
                    }
        }
        if (s + 1 < nstages) STOREB(wnext, buf ^ 1);
        __syncthreads();
    }
#undef PREFA
#undef LOADB
#undef STOREB

#pragma unroll
    for (int mt = 0; mt < 2; mt++)
#pragma unroll
        for (int nf = 0; nf < 4; nf++) {
            int mrow = m0 + wm * 32 + mt * 16 + (lane >> 2);
            int ncol = n0 + wn * 32 + (nf >> 1) * 16 + (nf & 1) * 8 + 2 * (lane & 3);
#pragma unroll
            for (int e = 0; e < 4; e++) {
                int m = mrow + (e >> 1) * 8;
                int n = ncol + (e & 1);
                float v = acc[mt][nf][e] + bias[n];
                __nv_bfloat16 h = __float2bfloat16(v);
                size_t o = (size_t)((n >> 7) * 128 + m) * 128 + (n & 127);
                outh[o] = h;
                outl[o] = __float2bfloat16(v - __bfloat162float(h));
            }
        }
}

// ---------------------------------------------------------------------------
// SIMT fp32 GEMM for FC1 (MODE 1) and L4 (MODE 3).
// ---------------------------------------------------------------------------
template<int BM, int BN, int TM, int TN, int MODE>
__global__ __launch_bounds__(256)
void gemm_k(const float* __restrict__ A, const float* __restrict__ W,
            const float* __restrict__ bias, float* __restrict__ out,
            int M, int N, int K, int co, long long ustr) {
    __shared__ float As[16][BM + 4];
    __shared__ float Ws[16][BN + 4];
    const int tid = threadIdx.x;
    const int tx = tid & 15, ty = tid >> 4;
    const int m0 = blockIdx.y * BM, n0 = blockIdx.x * BN;

    float acc[TM][TN];
#pragma unroll
    for (int i = 0; i < TM; i++)
#pragma unroll
        for (int j = 0; j < TN; j++) acc[i][j] = 0.0f;

    for (int k0 = 0; k0 < K; k0 += 16) {
#pragma unroll
        for (int r = 0; r < BM / 64; r++) {
            int lid = tid + r * 256;
            int row = lid >> 2;
            int kq = (lid & 3) << 2;
            float4 a = *(const float4*)(A + (size_t)(m0 + row) * K + (k0 + kq));
            As[kq + 0][row] = a.x;
            As[kq + 1][row] = a.y;
            As[kq + 2][row] = a.z;
            As[kq + 3][row] = a.w;
        }
#pragma unroll
        for (int r = 0; r < BN / 64; r++) {
            int lid = tid + r * 256;
            int k = lid / (BN / 4);
            int n4 = (lid % (BN / 4)) * 4;
            int gc = n0 + n4;
            float4 w;
            if (((N & 3) == 0) && gc + 4 <= N) {
                w = *(const float4*)(W + (size_t)(k0 + k) * N + gc);
            } else {
                w.x = (gc + 0 < N) ? W[(size_t)(k0 + k) * N + gc + 0] : 0.f;
                w.y = (gc + 1 < N) ? W[(size_t)(k0 + k) * N + gc + 1] : 0.f;
                w.z = (gc + 2 < N) ? W[(size_t)(k0 + k) * N + gc + 2] : 0.f;
                w.w = (gc + 3 < N) ? W[(size_t)(k0 + k) * N + gc + 3] : 0.f;
            }
            *(float4*)&Ws[k][n4] = w;
        }
        __syncthreads();

#pragma unroll
        for (int k = 0; k < 16; k++) {
            float a[TM], w[TN];
#pragma unroll
            for (int i = 0; i < TM / 4; i++)
                *(float4*)&a[4 * i] = *(const float4*)&As[k][ty * TM + 4 * i];
#pragma unroll
            for (int j = 0; j < TN / 4; j++)
                *(float4*)&w[4 * j] = *(const float4*)&Ws[k][tx * TN + 4 * j];
#pragma unroll
            for (int i = 0; i < TM; i++)
#pragma unroll
                for (int j = 0; j < TN; j++) acc[i][j] += a[i] * w[j];
        }
        __syncthreads();
    }

#pragma unroll
    for (int i = 0; i < TM; i++) {
        int m = m0 + ty * TM + i;
#pragma unroll
        for (int j = 0; j < TN; j++) {
            int n = n0 + tx * TN + j;
            if (n >= N) continue;
            float v = acc[i][j];
            if (MODE == 1) {
                v += bias[n];
                v = v > 0.f ? v : 0.f;
                out[(size_t)m * N + n] = v;
            } else {
                int t = n / co;
                out[(size_t)t * (size_t)ustr + (size_t)m * co + (n - t * co)] = v;
            }
        }
    }
}

// ---------------------------------------------------------------------------
// Props (CSR slice selected by nb):
//   Y[v] = U1[v>>shU] + 2 * sum_e w * U2[src>>shU]
//   out[v] = act( U0[v>>shU] + sum_e w * Y[src] + bias )
// ---------------------------------------------------------------------------
__global__ void propY_kernel(float4* __restrict__ Y, const float4* __restrict__ U1,
                             const float4* __restrict__ U2, int R4, int shU, int nb) {
    int v = blockIdx.y;
    int j = blockIdx.x * blockDim.x + threadIdx.x;
    float4 acc = make_float4(0.f, 0.f, 0.f, 0.f);
    int s = g_off[nb + v], t = g_off[nb + v + 1];
    for (int q = s; q < t; q++) {
        float w = g_cw[q];
        float4 x = U2[(size_t)(g_csrc[q] >> shU) * R4 + j];
        acc.x += w * x.x; acc.y += w * x.y; acc.z += w * x.z; acc.w += w * x.w;
    }
    float4 u1 = U1[(size_t)(v >> shU) * R4 + j];
    acc.x = u1.x + 2.f * acc.x;
    acc.y = u1.y + 2.f * acc.y;
    acc.z = u1.z + 2.f * acc.z;
    acc.w = u1.w + 2.f * acc.w;
    Y[(size_t)v * R4 + j] = acc;
}

// OUTF: 0 -> fp32 out; 1 -> bf16 hi/lo split (feeds next mma GEMM)
template<int OUTF>
__global__ void propF_kernel(float* __restrict__ outf,
                             __nv_bfloat16* __restrict__ outh,
                             __nv_bfloat16* __restrict__ outl,
                             const float4* __restrict__ U0, const float4* __restrict__ Y,
                             const float* __restrict__ bias, int R4, int comask,
                             int shU, int nb) {
    int v = blockIdx.y;
    int j = blockIdx.x * blockDim.x + threadIdx.x;
    float4 acc = U0[(size_t)(v >> shU) * R4 + j];
    int s = g_off[nb + v], t = g_off[nb + v + 1];
    for (int q = s; q < t; q++) {
        float w = g_cw[q];
        float4 y = Y[(size_t)g_csrc[q] * R4 + j];
        acc.x += w * y.x; acc.y += w * y.y; acc.z += w * y.z; acc.w += w * y.w;
    }
    int c0 = (4 * j) & comask;
    float4 bb = *(const float4*)&bias[c0];
    acc.x += bb.x; acc.y += bb.y; acc.z += bb.z; acc.w += bb.w;
    acc.x = acc.x >= 0.f ? acc.x : LRELU_S * acc.x;
    acc.y = acc.y >= 0.f ? acc.y : LRELU_S * acc.y;
    acc.z = acc.z >= 0.f ? acc.z : LRELU_S * acc.z;
    acc.w = acc.w >= 0.f ? acc.w : LRELU_S * acc.w;
    if (OUTF == 0) {
        ((float4*)outf)[(size_t)v * R4 + j] = acc;
    } else {
        size_t o = (size_t)v * R4 * 4 + 4 * j;
        __nv_bfloat16 h[4], l[4];
        float vv[4] = {acc.x, acc.y, acc.z, acc.w};
#pragma unroll
        for (int e = 0; e < 4; e++) {
            h[e] = __float2bfloat16(vv[e]);
            l[e] = __float2bfloat16(vv[e] - __bfloat162float(h[e]));
        }
        *(uint2*)(outh + o) = *(uint2*)h;
        *(uint2*)(outl + o) = *(uint2*)l;
    }
}

__global__ void propF3_kernel(float* __restrict__ out, const float* __restrict__ U0,
                              const float* __restrict__ Y,
                              const float* __restrict__ bias, int nb) {
    int v = blockIdx.y;
    int p = blockIdx.x * blockDim.x + threadIdx.x;   // < 384
    float acc = U0[(size_t)v * 384 + p];
    int s = g_off[nb + v], t = g_off[nb + v + 1];
    for (int q = s; q < t; q++)
        acc += g_cw[q] * Y[(size_t)g_csrc[q] * 384 + p];
    out[(size_t)v * 384 + p] = acc + bias[p % 3];
}

__global__ void final_kernel(float* __restrict__ out, const float* __restrict__ h,
                             const void* __restrict__ perm) {
    int i = blockIdx.x * blockDim.x + threadIdx.x;
    const int TOT = 128 * 6890 * 3;
    if (i < TOT) {
        int b = i / (6890 * 3);
        int r = i - b * (6890 * 3);
        int u = r / 3;
        int k = r - u * 3;
        int v = read_idx(perm, u);
        out[i] = h[(size_t)(v * 128 + b) * 3 + k];
    }
}

// ---------------------------------------------------------------------------
extern "C" void kernel_launch(void* const* d_in, const int* in_sizes, int n_in,
                              void* d_out, int out_size) {
    const float* x   = (const float*)d_in[0];
    const float* fw1 = (const float*)d_in[1];
    const float* fb1 = (const float*)d_in[2];
    const float* fw2 = (const float*)d_in[3];
    const float* fb2 = (const float*)d_in[4];
    const float* W[5];
    const float* bb[5];
    for (int i = 0; i < 5; i++) {
        W[i]  = (const float*)d_in[5 + 2 * i];
        bb[i] = (const float*)d_in[6 + 2 * i];
    }
    const void* edges[4];
    for (int i = 0; i < 4; i++) edges[i] = d_in[15 + i];
    const void* perm = d_in[19];
    float* out = (float*)d_out;

    float *T, *OA, *YB, *H1, *WC;
    __nv_bfloat16 *AH, *AL, *WTH, *WTL, *H1H, *H1L;
    cudaGetSymbolAddress((void**)&T,   g_T);
    cudaGetSymbolAddress((void**)&OA,  g_outA);
    cudaGetSymbolAddress((void**)&YB,  g_Y);
    cudaGetSymbolAddress((void**)&H1,  g_h1);
    cudaGetSymbolAddress((void**)&WC,  g_wc);
    cudaGetSymbolAddress((void**)&AH,  g_Ah);
    cudaGetSymbolAddress((void**)&AL,  g_Al);
    cudaGetSymbolAddress((void**)&WTH, g_wth);
    cudaGetSymbolAddress((void**)&WTL, g_wtl);
    cudaGetSymbolAddress((void**)&H1H, g_h1h);
    cudaGetSymbolAddress((void**)&H1L, g_h1l);

    const int DSM = 2 * GBUF;   // 96KB double buffer
    cudaFuncSetAttribute(gemm_mmab<64>,
                         cudaFuncAttributeMaxDynamicSharedMemorySize, DSM);
    cudaFuncSetAttribute(gemm_mmab<32>,
                         cudaFuncAttributeMaxDynamicSharedMemorySize, DSM);
    cudaFuncSetAttribute(gemm_fc2d,
                         cudaFuncAttributeMaxDynamicSharedMemorySize, DSM);

    const int ns[5]   = {864, 1728, 3456, 6912, 6912};
    const int cis[5]  = {128, 128, 64, 32, 16};
    const int cos_[5] = {128, 64, 32, 16, 3};
    const int col2[5] = {7, 6, 5, 4, 0};
    const int nbArr[5] = {0, 864, 2592, 6048, 6048};

    // 0: FC1 (SIMT)
    gemm_k<128, 128, 8, 8, 1><<<dim3(4, 1), 256>>>(x, fw1, fb1, H1,
                                                   128, 512, 128, 0, 0);
    // 1: split FC1 output
    hsplit_kernel<<<256, 256>>>(H1, H1H, H1L);
    // 2: combined weights for layer 0
    wprep_kernel<<<(384 * 128 + 255) / 256, 256>>>(W[0], WC, WTH, WTL, 128, 128, 384);
    // 3: FC2 GEMM, direct fp32 B (no tsplit) — ncu capture target
    gemm_fc2d<<<dim3(110592 / 64, 1), 256, DSM>>>(
        H1H, H1L, fw2, fb2, AH, AL, 128, 110592, 512);
    // 4: layer-0 ChebConv GEMM
    gemm_mmab<64><<<dim3(6, 864), 256, DSM>>>(AH, AL, WTH, WTL, T,
                                              110592, 384, 128, 7, 14155776LL);
    // 5: dtype sniff, then fused CSR build
    detect_kernel<<<1, 256>>>((const int*)edges[0], 5184);
    csr_zero_kernel<<<(12960 + 255) / 256, 256>>>();
    csr_count_kernel<<<dim3(162, 4), 256>>>(edges[0], edges[1], edges[2], edges[3]);
    csr_dinv_kernel<<<(12960 + 255) / 256, 256>>>();
    csr_scan_kernel<<<4, 1024>>>();
    csr_fill_kernel<<<dim3(162, 4), 256>>>(edges[0], edges[1], edges[2], edges[3]);

    for (int l = 0; l < 5; l++) {
        int n  = ns[l];
        int ci = cis[l];
        int co = cos_[l];
        int N  = 3 * co;
        int Np = ((N + 63) / 64) * 64;
        int ng = (l == 0 || l == 4) ? n : n / 2;   // layers 1-3 un-repeated
        int Mg = ng * 128;
        int shU = (l == 0 || l == 4) ? 0 : 1;
        int R4 = 32 * co;
        long long US = (long long)Mg * co;
        int nb = nbArr[l];

        if (l > 0) {
            wprep_kernel<<<(Np * ci + 255) / 256, 256>>>(W[l], WC, WTH, WTL,
                                                         ci, co, Np);
            if (l < 4) {   // mma path (128x64 tile)
                if (ci % 64 == 0)
                    gemm_mmab<64><<<dim3(Np / 64, Mg / 128), 256, DSM>>>(
                        AH, AL, WTH, WTL, T, Mg, N, ci, col2[l], US);
                else
                    gemm_mmab<32><<<dim3(Np / 64, Mg / 128), 256, DSM>>>(
                        AH, AL, WTH, WTL, T, Mg, N, ci, col2[l], US);
            } else {       // L4: K=16, SIMT
                gemm_k<256, 64, 16, 4, 3><<<dim3(1, Mg / 256), 256>>>(
                    OA, WC, nullptr, T, Mg, N, ci, co, US);
            }
        }

        // Y = U1' + 2*P*U2'
        propY_kernel<<<dim3(R4 >= 256 ? R4 / 256 : 1, n), R4 < 256 ? R4 : 256>>>(
            (float4*)YB, (const float4*)(T + US), (const float4*)(T + 2 * US),
            R4, shU, nb);
        // out = act(U0' + P*Y + b)
        if (l < 3) {
            propF_kernel<1><<<dim3(R4 / 256, n), 256>>>(
                nullptr, AH, AL, (const float4*)T, (const float4*)YB,
                bb[l], R4, co - 1, shU, nb);
        } else if (l == 3) {
            propF_kernel<0><<<dim3(R4 / 256, n), 256>>>(
                OA, nullptr, nullptr, (const float4*)T, (const float4*)YB,
                bb[l], R4, co - 1, shU, nb);
        } else {
            propF3_kernel<<<dim3(3, n), 128>>>(OA, T, YB, bb[4], nb);
        }
    }

    const int TOT = 128 * 6890 * 3;
    final_kernel<<<(TOT + 255) / 256, 256>>>(out, OA, perm);
}

// round 15
// speedup vs baseline: 1.2938x; 1.1686x over previous
#include <cuda_runtime.h>
#include <cuda_fp16.h>
#include <cstdint>

// ---------------------------------------------------------------------------
// ChebGcnDecoder, commuted form. GEMMs on mma.sync fp16 with asymmetric
// split: A = hi+lo fp16 (~22-bit), B single fp16 for FC2/L0 (2 MMAs/k-step)
// and hi/lo fp16 for L1-L3 (3 MMAs, ~fp32). cp.async double-buffered smem,
// 128x64 tiles. FC2 streams fp32 weights directly (in-kernel fp16 convert).
// ---------------------------------------------------------------------------

#define LRELU_S 0.2f

__device__ float g_T[42467328];            // U0|U1|U2, stride Mg*co
__device__ float g_outA[14155776];         // fp32 layer output (l=3)
__device__ float g_Y[14155776];            // Y = U1 + 2*P*U2
__device__ __half g_Ah[14155776];          // fp16-hi GEMM input (activations)
__device__ __half g_Al[14155776];          // fp16-lo
__device__ float g_h1[65536];              // FC1 output 128x512 fp32
__device__ __half g_h1h[65536];
__device__ __half g_h1l[65536];
__device__ float g_wc[4096];               // combined weights fp32 (KxN), L4 only
__device__ __half g_wth[98304];            // combined weights fp16-hi (Np x K), all layers
__device__ __half g_wtl[98304];            // fp16-lo
__device__ int   g_cnt[12960];
__device__ float g_dinv[12960];
__device__ int   g_off[12961];
__device__ int   g_cur[12960];
__device__ int   g_csrc[77760];
__device__ float g_cw[77760];
__device__ int   g_is64;

__constant__ int c_nb[4] = {0, 864, 2592, 6048};
__constant__ int c_eb[4] = {0, 5184, 15552, 36288};
__constant__ int c_nl[4] = {864, 1728, 3456, 6912};
// wprep_all tables (5 layers): ci, co, Np, fp16-Wt offset
__constant__ int c_wci[5]  = {128, 128, 64, 32, 16};
__constant__ int c_wco[5]  = {128, 64, 32, 16, 3};
__constant__ int c_wnp[5]  = {384, 192, 128, 64, 0};
__constant__ int c_woff[5] = {0, 49152, 73728, 81920, 0};

// ---------------------------------------------------------------------------
__device__ __forceinline__ int read_idx(const void* p, int i) {
    if (g_is64) return (int)((const long long*)p)[i];
    return ((const int*)p)[i];
}

__global__ void detect_kernel(const int* w, int nwords) {
    __shared__ int any;
    if (threadIdx.x == 0) any = 0;
    __syncthreads();
    int a = 0;
    for (int i = 1 + 2 * (int)threadIdx.x; i < nwords; i += 2 * blockDim.x) a |= w[i];
    if (a) atomicOr(&any, 1);
    __syncthreads();
    if (threadIdx.x == 0) g_is64 = any ? 0 : 1;
}

// ---- fused CSR build over all 4 graphs ----
__global__ void csr_zero_kernel() {
    int i = blockIdx.x * blockDim.x + threadIdx.x;
    if (i < 12960) g_cnt[i] = 0;
}

__global__ void csr_count_kernel(const void* e0, const void* e1,
                                 const void* e2, const void* e3) {
    int l = blockIdx.y;
    const void* eg = (l == 0) ? e0 : (l == 1) ? e1 : (l == 2) ? e2 : e3;
    int e = 6 * c_nl[l];
    int i = blockIdx.x * blockDim.x + threadIdx.x;
    if (i < e) atomicAdd(&g_cnt[c_nb[l] + read_idx(eg, e + i)], 1);
}

__global__ void csr_dinv_kernel() {
    int i = blockIdx.x * blockDim.x + threadIdx.x;
    if (i < 12960) g_dinv[i] = (g_cnt[i] > 0) ? rsqrtf((float)g_cnt[i]) : 0.0f;
}

__global__ void csr_scan_kernel() {
    __shared__ int partial[1024];
    int l = blockIdx.x;
    int n = c_nl[l], nb = c_nb[l], eb = c_eb[l];
    int tid = threadIdx.x;
    int C = (n + 1023) / 1024;
    int start = tid * C;
    int local[8];
    int s = 0;
    for (int i = 0; i < C; i++) {
        int idx = start + i;
        int v = (idx < n) ? g_cnt[nb + idx] : 0;
        local[i] = s;
        s += v;
    }
    partial[tid] = s;
    __syncthreads();
    for (int d = 1; d < 1024; d <<= 1) {
        int t = (tid >= d) ? partial[tid - d] : 0;
        __syncthreads();
        if (tid >= d) partial[tid] += t;
        __syncthreads();
    }
    int base = (tid > 0) ? partial[tid - 1] : 0;
    for (int i = 0; i < C; i++) {
        int idx = start + i;
        if (idx < n) {
            int o = eb + base + local[i];
            g_off[nb + idx] = o;
            g_cur[nb + idx] = o;
        }
    }
    if (l == 3 && tid == 1023) g_off[12960] = 77760;
}

__global__ void csr_fill_kernel(const void* e0, const void* e1,
                                const void* e2, const void* e3) {
    int l = blockIdx.y;
    const void* eg = (l == 0) ? e0 : (l == 1) ? e1 : (l == 2) ? e2 : e3;
    int e = 6 * c_nl[l];
    int nb = c_nb[l];
    int i = blockIdx.x * blockDim.x + threadIdx.x;
    if (i < e) {
        int s = read_idx(eg, i);
        int d = read_idx(eg, e + i);
        int p = atomicAdd(&g_cur[nb + d], 1);
        g_csrc[p] = s;
        g_cw[p] = -g_dinv[nb + s] * g_dinv[nb + d];
    }
}

// Combined weights for ALL layers in one launch. [W0-W2 | W1 | W2].
// Layers 0-3: fp16 hi/lo transposed (Np x K) at c_woff[l].
// Layer 4: fp32 Wc (K x N) only (SIMT path).
__global__ void wprep_all(const float* __restrict__ Wa, const float* __restrict__ Wb,
                          const float* __restrict__ Wc2, const float* __restrict__ Wd,
                          const float* __restrict__ We,
                          __half* __restrict__ Wth, __half* __restrict__ Wtl,
                          float* __restrict__ Wc) {
    int l = blockIdx.y;
    const float* W = (l == 0) ? Wa : (l == 1) ? Wb : (l == 2) ? Wc2
                     : (l == 3) ? Wd : We;
    int ci = c_wci[l], co = c_wco[l];
    int N = 3 * co;
    int i = blockIdx.x * blockDim.x + threadIdx.x;
    int cico = ci * co;
    if (l == 4) {
        if (i >= ci * N) return;
        int k = i / N, n = i - k * N;
        float v;
        if (n < co)            v = W[k * co + n] - W[2 * cico + k * co + n];
        else if (n < 2 * co)   v = W[cico + k * co + (n - co)];
        else                   v = W[2 * cico + k * co + (n - 2 * co)];
        Wc[k * N + n] = v;
        return;
    }
    int Np = c_wnp[l];
    if (i >= Np * ci) return;
    int n = i / ci, k = i - n * ci;
    float v = 0.f;
    if (n < N) {
        if (n < co)            v = W[k * co + n] - W[2 * cico + k * co + n];
        else if (n < 2 * co)   v = W[cico + k * co + (n - co)];
        else                   v = W[2 * cico + k * co + (n - 2 * co)];
    }
    __half h = __float2half(v);
    Wth[c_woff[l] + n * ci + k] = h;
    Wtl[c_woff[l] + n * ci + k] = __float2half(v - __half2float(h));
}

// split FC1 output (128x512) into fp16 hi/lo
__global__ void hsplit_kernel(const float* __restrict__ in,
                              __half* __restrict__ outh,
                              __half* __restrict__ outl) {
    int i = blockIdx.x * blockDim.x + threadIdx.x;
    if (i < 65536) {
        float v = in[i];
        __half h = __float2half(v);
        outh[i] = h;
        outl[i] = __float2half(v - __half2float(h));
    }
}

// ---------------------------------------------------------------------------
__device__ __forceinline__ uint32_t smem_u32(const void* p) {
    uint32_t a;
    asm("{ .reg .u64 t; cvta.to.shared.u64 t, %1; cvt.u32.u64 %0, t; }"
        : "=r"(a) : "l"(p));
    return a;
}

__device__ __forceinline__ void cp_async16(uint32_t dst, const void* src) {
    asm volatile("cp.async.cg.shared.global [%0], [%1], 16;"
                 :: "r"(dst), "l"(src));
}

#define LDSM_X4(r0, r1, r2, r3, a)                                            \
    asm volatile("ldmatrix.sync.aligned.m8n8.x4.shared.b16 {%0,%1,%2,%3}, [%4];" \
        : "=r"(r0), "=r"(r1), "=r"(r2), "=r"(r3) : "r"(a))

#define MMA4H(c, a, b0, b1)                                                   \
    asm volatile(                                                             \
        "mma.sync.aligned.m16n8k16.row.col.f32.f16.f16.f32 "                  \
        "{%0,%1,%2,%3}, {%4,%5,%6,%7}, {%8,%9}, {%0,%1,%2,%3};\n"             \
        : "+f"((c)[0]), "+f"((c)[1]), "+f"((c)[2]), "+f"((c)[3])              \
        : "r"((a)[0]), "r"((a)[1]), "r"((a)[2]), "r"((a)[3]),                 \
          "r"(b0), "r"(b1))

// ---------------------------------------------------------------------------
// 128x64-tile fp16 GEMM for the layer GEMMs. NSPLIT=2: B single (2 MMAs);
// NSPLIT=3: B hi/lo (3 MMAs). Inputs pre-split. Wt is (Np x K) row-major.
// Epilogue: paired float2 split-write into U0|U1|U2 at out + t*ustr (fp32).
// ---------------------------------------------------------------------------
template<int KC, int NSPLIT>
__global__ __launch_bounds__(256)
void gemm_mmab(const __half* __restrict__ Ah, const __half* __restrict__ Al,
               const __half* __restrict__ Wh, const __half* __restrict__ Wl,
               float* __restrict__ out,
               int M, int N, int K, int coLog2, long long ustr) {
    extern __shared__ __align__(128) uint8_t smdyn[];
    constexpr uint32_t BUFSZ = (NSPLIT == 3) ? 49152 : 40960;
    const uint32_t sb = smem_u32(smdyn);
    const uint32_t oAh = 0, oAl = 16384, oBh = 32768, oBl = 40960;

    const int tid = threadIdx.x, lane = tid & 31, warp = tid >> 5;
    const int wm = warp & 3, wn = warp >> 2;
    const int m0 = blockIdx.y * 128, n0 = blockIdx.x * 64;

    float acc[2][4][4];
#pragma unroll
    for (int i = 0; i < 2; i++)
#pragma unroll
        for (int j = 0; j < 4; j++)
#pragma unroll
            for (int q = 0; q < 4; q++) acc[i][j][q] = 0.f;

    const uint32_t lq = lane >> 3, lr = lane & 7;
    const uint32_t qk = (lq >> 1) << 4;
    uint32_t aoff[2], asw[2], boff[2], bsw[2];
#pragma unroll
    for (int mt = 0; mt < 2; mt++) {
        int row = wm * 32 + mt * 16 + ((lq & 1) << 3) + lr;
        aoff[mt] = (uint32_t)row * 128;
        asw[mt] = (uint32_t)((row & 7) << 4);
    }
#pragma unroll
    for (int nt = 0; nt < 2; nt++) {
        int row = wn * 32 + nt * 16 + ((lq & 1) << 3) + lr;
        boff[nt] = (uint32_t)row * 128;
        bsw[nt] = (uint32_t)((row & 7) << 4);
    }

    constexpr int RPR = KC / 8;
    const int nstages = K / KC;

#define PREFETCH(S, BUF) do {                                                 \
        int k0_ = (S) * KC;                                                   \
        uint32_t bo_ = sb + (BUF) * BUFSZ;                                    \
        _Pragma("unroll")                                                     \
        for (int r = 0; r < KC / 16; r++) {                                   \
            int idx = r * 256 + tid;                                          \
            int row = idx / RPR, c8 = idx % RPR;                              \
            size_t go = (size_t)(m0 + row) * K + k0_ + c8 * 8;                \
            uint32_t so = (uint32_t)row * 128 +                               \
                          (((uint32_t)c8 * 16) ^ ((row & 7) << 4));           \
            cp_async16(bo_ + oAh + so, Ah + go);                              \
            cp_async16(bo_ + oAl + so, Al + go);                              \
        }                                                                     \
        _Pragma("unroll")                                                     \
        for (int r = 0; r < KC / 32; r++) {                                   \
            int idx = r * 256 + tid;                                          \
            int row = idx / RPR, c8 = idx % RPR;                              \
            size_t go = (size_t)(n0 + row) * K + k0_ + c8 * 8;                \
            uint32_t so = (uint32_t)row * 128 +                               \
                          (((uint32_t)c8 * 16) ^ ((row & 7) << 4));           \
            cp_async16(bo_ + oBh + so, Wh + go);                              \
            if (NSPLIT == 3) cp_async16(bo_ + oBl + so, Wl + go);             \
        }                                                                     \
        asm volatile("cp.async.commit_group;" ::: "memory");                  \
    } while (0)

    PREFETCH(0, 0);

    for (int s = 0; s < nstages; s++) {
        int buf = s & 1;
        if (s + 1 < nstages) {
            PREFETCH(s + 1, buf ^ 1);
            asm volatile("cp.async.wait_group 1;" ::: "memory");
        } else {
            asm volatile("cp.async.wait_group 0;" ::: "memory");
        }
        __syncthreads();

        uint32_t bo = sb + buf * BUFSZ;
#pragma unroll
        for (int kk = 0; kk < KC / 16; kk++) {
            uint32_t cb = ((uint32_t)kk << 5) + qk;
            uint32_t ah[2][4], al[2][4], bh[2][4], bl[2][4];
#pragma unroll
            for (int mt = 0; mt < 2; mt++) {
                uint32_t ad = bo + oAh + aoff[mt] + (cb ^ asw[mt]);
                LDSM_X4(ah[mt][0], ah[mt][1], ah[mt][2], ah[mt][3], ad);
                LDSM_X4(al[mt][0], al[mt][1], al[mt][2], al[mt][3], ad + 16384);
            }
#pragma unroll
            for (int nt = 0; nt < 2; nt++) {
                uint32_t bd = bo + oBh + boff[nt] + (cb ^ bsw[nt]);
                LDSM_X4(bh[nt][0], bh[nt][1], bh[nt][2], bh[nt][3], bd);
                if (NSPLIT == 3)
                    LDSM_X4(bl[nt][0], bl[nt][1], bl[nt][2], bl[nt][3], bd + 8192);
            }
#pragma unroll
            for (int mt = 0; mt < 2; mt++)
#pragma unroll
                for (int nt = 0; nt < 2; nt++)
#pragma unroll
                    for (int u = 0; u < 2; u++) {
                        int nf = nt * 2 + u;
                        MMA4H(acc[mt][nf], ah[mt], bh[nt][u], bh[nt][u + 2]);
                        MMA4H(acc[mt][nf], al[mt], bh[nt][u], bh[nt][u + 2]);
                        if (NSPLIT == 3)
                            MMA4H(acc[mt][nf], ah[mt], bl[nt][u], bl[nt][u + 2]);
                    }
        }
        __syncthreads();
    }
#undef PREFETCH

#pragma unroll
    for (int mt = 0; mt < 2; mt++)
#pragma unroll
        for (int nf = 0; nf < 4; nf++) {
            int mrow = m0 + wm * 32 + mt * 16 + (lane >> 2);
            int ncol = n0 + wn * 32 + (nf >> 1) * 16 + (nf & 1) * 8 + 2 * (lane & 3);
#pragma unroll
            for (int half = 0; half < 2; half++) {    // rows m, m+8
                int m = mrow + half * 8;
                int n = ncol;
                if (n < N) {    // N even, n even -> n+1 < N too; same t-block
                    int t = n >> coLog2;
                    int cc = n & ((1 << coLog2) - 1);
                    float2 v2 = make_float2(acc[mt][nf][half * 2],
                                            acc[mt][nf][half * 2 + 1]);
                    *(float2*)(out + (size_t)t * (size_t)ustr
                               + ((size_t)m << coLog2) + cc) = v2;
                }
            }
        }
}

// ---------------------------------------------------------------------------
// FC2 GEMM: A pre-split fp16 (128 x 512), B streamed from fp32 fc_w2 with
// in-kernel SINGLE fp16 convert (2-MMA split). Epilogue: bias + fp16 hi/lo
// paired writes to (node,batch,ch) layout.
// ---------------------------------------------------------------------------
#define FBUF 40960

__global__ __launch_bounds__(256)
void gemm_fc2d(const __half* __restrict__ Ah, const __half* __restrict__ Al,
               const float* __restrict__ W, const float* __restrict__ bias,
               __half* __restrict__ outh, __half* __restrict__ outl,
               int M, int N, int K) {
    extern __shared__ __align__(128) uint8_t smdyn[];
    const uint32_t sb = smem_u32(smdyn);
    const uint32_t oAh = 0, oAl = 16384, oBh = 32768;

    const int tid = threadIdx.x, lane = tid & 31, warp = tid >> 5;
    const int wm = warp & 3, wn = warp >> 2;
    const int m0 = blockIdx.y * 128, n0 = blockIdx.x * 64;

    float acc[2][4][4];
#pragma unroll
    for (int i = 0; i < 2; i++)
#pragma unroll
        for (int j = 0; j < 4; j++)
#pragma unroll
            for (int q = 0; q < 4; q++) acc[i][j][q] = 0.f;

    const uint32_t lq = lane >> 3, lr = lane & 7;
    const uint32_t qk = (lq >> 1) << 4;
    uint32_t aoff[2], asw[2], boff[2], bsw[2];
#pragma unroll
    for (int mt = 0; mt < 2; mt++) {
        int row = wm * 32 + mt * 16 + ((lq & 1) << 3) + lr;
        aoff[mt] = (uint32_t)row * 128;
        asw[mt] = (uint32_t)((row & 7) << 4);
    }
#pragma unroll
    for (int nt = 0; nt < 2; nt++) {
        int row = wn * 32 + nt * 16 + ((lq & 1) << 3) + lr;
        boff[nt] = (uint32_t)row * 128;
        bsw[nt] = (uint32_t)((row & 7) << 4);
    }

    const int kp0 = tid >> 6;            // base k-pair, step 4 per r
    const int nn  = tid & 63;
    const int gn  = n0 + nn;
    const uint32_t bso = (uint32_t)nn * 128;
    const uint32_t bsw2 = (uint32_t)((nn & 7) << 4);

    const int nstages = K >> 6;          // KC = 64

#define PREFA(S, BUF) do {                                                    \
        int k0_ = (S) << 6;                                                   \
        uint32_t bo_ = sb + (BUF) * FBUF;                                     \
        _Pragma("unroll")                                                     \
        for (int r = 0; r < 4; r++) {                                         \
            int idx = r * 256 + tid;                                          \
            int row = idx >> 3, c8 = idx & 7;                                 \
            size_t go = (size_t)(m0 + row) * K + k0_ + c8 * 8;                \
            uint32_t so = (uint32_t)row * 128 +                               \
                          (((uint32_t)c8 * 16) ^ ((row & 7) << 4));           \
            cp_async16(bo_ + oAh + so, Ah + go);                              \
            cp_async16(bo_ + oAl + so, Al + go);                              \
        }                                                                     \
        asm volatile("cp.async.commit_group;" ::: "memory");                  \
    } while (0)

#define LOADB(S, wreg) do {                                                   \
        int k0_ = (S) << 6;                                                   \
        _Pragma("unroll")                                                     \
        for (int r = 0; r < 8; r++) {                                         \
            int kp = kp0 + r * 4;                                             \
            (wreg)[2 * r]     = W[(size_t)(k0_ + 2 * kp) * N + gn];           \
            (wreg)[2 * r + 1] = W[(size_t)(k0_ + 2 * kp + 1) * N + gn];       \
        }                                                                     \
    } while (0)

#define STOREB(wreg, BUF) do {                                                \
        uint32_t bo_ = (BUF) * FBUF;                                          \
        _Pragma("unroll")                                                     \
        for (int r = 0; r < 8; r++) {                                         \
            int kp = kp0 + r * 4;                                             \
            __half2 h;                                                        \
            h.x = __float2half((wreg)[2 * r]);                                \
            h.y = __float2half((wreg)[2 * r + 1]);                            \
            uint32_t o = bso + (((uint32_t)(4 * kp)) ^ bsw2);                 \
            *(__half2*)(smdyn + bo_ + oBh + o) = h;                           \
        }                                                                     \
    } while (0)

    float wcur[16];
    PREFA(0, 0);
    LOADB(0, wcur);
    STOREB(wcur, 0);

    for (int s = 0; s < nstages; s++) {
        int buf = s & 1;
        float wnext[16];
        if (s + 1 < nstages) {
            PREFA(s + 1, buf ^ 1);
            LOADB(s + 1, wnext);           // LDG latency hides under MMAs
            asm volatile("cp.async.wait_group 1;" ::: "memory");
        } else {
            asm volatile("cp.async.wait_group 0;" ::: "memory");
        }
        __syncthreads();

        uint32_t bo = sb + buf * FBUF;
#pragma unroll
        for (int kk = 0; kk < 4; kk++) {
            uint32_t cb = ((uint32_t)kk << 5) + qk;
            uint32_t ah[2][4], al[2][4], bh[2][4];
#pragma unroll
            for (int mt = 0; mt < 2; mt++) {
                uint32_t ad = bo + oAh + aoff[mt] + (cb ^ asw[mt]);
                LDSM_X4(ah[mt][0], ah[mt][1], ah[mt][2], ah[mt][3], ad);
                LDSM_X4(al[mt][0], al[mt][1], al[mt][2], al[mt][3], ad + 16384);
            }
#pragma unroll
            for (int nt = 0; nt < 2; nt++) {
                uint32_t bd = bo + oBh + boff[nt] + (cb ^ bsw[nt]);
                LDSM_X4(bh[nt][0], bh[nt][1], bh[nt][2], bh[nt][3], bd);
            }
#pragma unroll
            for (int mt = 0; mt < 2; mt++)
#pragma unroll
                for (int nt = 0; nt < 2; nt++)
#pragma unroll
                    for (int u = 0; u < 2; u++) {
                        int nf = nt * 2 + u;
                        MMA4H(acc[mt][nf], ah[mt], bh[nt][u], bh[nt][u + 2]);
                        MMA4H(acc[mt][nf], al[mt], bh[nt][u], bh[nt][u + 2]);
                    }
        }
        if (s + 1 < nstages) STOREB(wnext, buf ^ 1);
        __syncthreads();
    }
#undef PREFA
#undef LOADB
#undef STOREB

#pragma unroll
    for (int mt = 0; mt < 2; mt++)
#pragma unroll
        for (int nf = 0; nf < 4; nf++) {
            int mrow = m0 + wm * 32 + mt * 16 + (lane >> 2);
            int ncol = n0 + wn * 32 + (nf >> 1) * 16 + (nf & 1) * 8 + 2 * (lane & 3);
#pragma unroll
            for (int half = 0; half < 2; half++) {
                int m = mrow + half * 8;
                int n = ncol;       // n even; n, n+1 in same 128-ch block
                float v0 = acc[mt][nf][half * 2] + bias[n];
                float v1 = acc[mt][nf][half * 2 + 1] + bias[n + 1];
                __half2 h, l;
                h.x = __float2half(v0);
                l.x = __float2half(v0 - __half2float(h.x));
                h.y = __float2half(v1);
                l.y = __float2half(v1 - __half2float(h.y));
                size_t o = (size_t)((n >> 7) * 128 + m) * 128 + (n & 127);
                *(__half2*)(outh + o) = h;
                *(__half2*)(outl + o) = l;
            }
        }
}

// ---------------------------------------------------------------------------
// SIMT fp32 GEMM for FC1 (MODE 1) and L4 (MODE 3).
// ---------------------------------------------------------------------------
template<int BM, int BN, int TM, int TN, int MODE>
__global__ __launch_bounds__(256)
void gemm_k(const float* __restrict__ A, const float* __restrict__ W,
            const float* __restrict__ bias, float* __restrict__ out,
            int M, int N, int K, int co, long long ustr) {
    __shared__ float As[16][BM + 4];
    __shared__ float Ws[16][BN + 4];
    const int tid = threadIdx.x;
    const int tx = tid & 15, ty = tid >> 4;
    const int m0 = blockIdx.y * BM, n0 = blockIdx.x * BN;

    float acc[TM][TN];
#pragma unroll
    for (int i = 0; i < TM; i++)
#pragma unroll
        for (int j = 0; j < TN; j++) acc[i][j] = 0.0f;

    for (int k0 = 0; k0 < K; k0 += 16) {
#pragma unroll
        for (int r = 0; r < BM / 64; r++) {
            int lid = tid + r * 256;
            int row = lid >> 2;
            int kq = (lid & 3) << 2;
            float4 a = *(const float4*)(A + (size_t)(m0 + row) * K + (k0 + kq));
            As[kq + 0][row] = a.x;
            As[kq + 1][row] = a.y;
            As[kq + 2][row] = a.z;
            As[kq + 3][row] = a.w;
        }
#pragma unroll
        for (int r = 0; r < BN / 64; r++) {
            int lid = tid + r * 256;
            int k = lid / (BN / 4);
            int n4 = (lid % (BN / 4)) * 4;
            int gc = n0 + n4;
            float4 w;
            if (((N & 3) == 0) && gc + 4 <= N) {
                w = *(const float4*)(W + (size_t)(k0 + k) * N + gc);
            } else {
                w.x = (gc + 0 < N) ? W[(size_t)(k0 + k) * N + gc + 0] : 0.f;
                w.y = (gc + 1 < N) ? W[(size_t)(k0 + k) * N + gc + 1] : 0.f;
                w.z = (gc + 2 < N) ? W[(size_t)(k0 + k) * N + gc + 2] : 0.f;
                w.w = (gc + 3 < N) ? W[(size_t)(k0 + k) * N + gc + 3] : 0.f;
            }
            *(float4*)&Ws[k][n4] = w;
        }
        __syncthreads();

#pragma unroll
        for (int k = 0; k < 16; k++) {
            float a[TM], w[TN];
#pragma unroll
            for (int i = 0; i < TM / 4; i++)
                *(float4*)&a[4 * i] = *(const float4*)&As[k][ty * TM + 4 * i];
#pragma unroll
            for (int j = 0; j < TN / 4; j++)
                *(float4*)&w[4 * j] = *(const float4*)&Ws[k][tx * TN + 4 * j];
#pragma unroll
            for (int i = 0; i < TM; i++)
#pragma unroll
                for (int j = 0; j < TN; j++) acc[i][j] += a[i] * w[j];
        }
        __syncthreads();
    }

#pragma unroll
    for (int i = 0; i < TM; i++) {
        int m = m0 + ty * TM + i;
#pragma unroll
        for (int j = 0; j < TN; j++) {
            int n = n0 + tx * TN + j;
            if (n >= N) continue;
            float v = acc[i][j];
            if (MODE == 1) {
                v += bias[n];
                v = v > 0.f ? v : 0.f;
                out[(size_t)m * N + n] = v;
            } else {
                int t = n / co;
                out[(size_t)t * (size_t)ustr + (size_t)m * co + (n - t * co)] = v;
            }
        }
    }
}

// ---------------------------------------------------------------------------
// Props (CSR slice selected by nb):
//   Y[v] = U1[v>>shU] + 2 * sum_e w * U2[src>>shU]
//   out[v] = act( U0[v>>shU] + sum_e w * Y[src] + bias )
// ---------------------------------------------------------------------------
__global__ void propY_kernel(float4* __restrict__ Y, const float4* __restrict__ U1,
                             const float4* __restrict__ U2, int R4, int shU, int nb) {
    int v = blockIdx.y;
    int j = blockIdx.x * blockDim.x + threadIdx.x;
    float4 acc = make_float4(0.f, 0.f, 0.f, 0.f);
    int s = g_off[nb + v], t = g_off[nb + v + 1];
    for (int q = s; q < t; q++) {
        float w = g_cw[q];
        float4 x = U2[(size_t)(g_csrc[q] >> shU) * R4 + j];
        acc.x += w * x.x; acc.y += w * x.y; acc.z += w * x.z; acc.w += w * x.w;
    }
    float4 u1 = U1[(size_t)(v >> shU) * R4 + j];
    acc.x = u1.x + 2.f * acc.x;
    acc.y = u1.y + 2.f * acc.y;
    acc.z = u1.z + 2.f * acc.z;
    acc.w = u1.w + 2.f * acc.w;
    Y[(size_t)v * R4 + j] = acc;
}

// OUTF: 0 -> fp32 out; 1 -> fp16 hi/lo split (feeds next mma GEMM)
template<int OUTF>
__global__ void propF_kernel(float* __restrict__ outf,
                             __half* __restrict__ outh,
                             __half* __restrict__ outl,
                             const float4* __restrict__ U0, const float4* __restrict__ Y,
                             const float* __restrict__ bias, int R4, int comask,
                             int shU, int nb) {
    int v = blockIdx.y;
    int j = blockIdx.x * blockDim.x + threadIdx.x;
    float4 acc = U0[(size_t)(v >> shU) * R4 + j];
    int s = g_off[nb + v], t = g_off[nb + v + 1];
    for (int q = s; q < t; q++) {
        float w = g_cw[q];
        float4 y = Y[(size_t)g_csrc[q] * R4 + j];
        acc.x += w * y.x; acc.y += w * y.y; acc.z += w * y.z; acc.w += w * y.w;
    }
    int c0 = (4 * j) & comask;
    float4 bb = *(const float4*)&bias[c0];
    acc.x += bb.x; acc.y += bb.y; acc.z += bb.z; acc.w += bb.w;
    acc.x = acc.x >= 0.f ? acc.x : LRELU_S * acc.x;
    acc.y = acc.y >= 0.f ? acc.y : LRELU_S * acc.y;
    acc.z = acc.z >= 0.f ? acc.z : LRELU_S * acc.z;
    acc.w = acc.w >= 0.f ? acc.w : LRELU_S * acc.w;
    if (OUTF == 0) {
        ((float4*)outf)[(size_t)v * R4 + j] = acc;
    } else {
        size_t o = (size_t)v * R4 * 4 + 4 * j;
        __half h[4], l[4];
        float vv[4] = {acc.x, acc.y, acc.z, acc.w};
#pragma unroll
        for (int e = 0; e < 4; e++) {
            h[e] = __float2half(vv[e]);
            l[e] = __float2half(vv[e] - __half2float(h[e]));
        }
        *(uint2*)(outh + o) = *(uint2*)h;
        *(uint2*)(outl + o) = *(uint2*)l;
    }
}

__global__ void propF3_kernel(float* __restrict__ out, const float* __restrict__ U0,
                              const float* __restrict__ Y,
                              const float* __restrict__ bias, int nb) {
    int v = blockIdx.y;
    int p = blockIdx.x * blockDim.x + threadIdx.x;   // < 384
    float acc = U0[(size_t)v * 384 + p];
    int s = g_off[nb + v], t = g_off[nb + v + 1];
    for (int q = s; q < t; q++)
        acc += g_cw[q] * Y[(size_t)g_csrc[q] * 384 + p];
    out[(size_t)v * 384 + p] = acc + bias[p % 3];
}

__global__ void final_kernel(float* __restrict__ out, const float* __restrict__ h,
                             const void* __restrict__ perm) {
    int i = blockIdx.x * blockDim.x + threadIdx.x;
    const int TOT = 128 * 6890 * 3;
    if (i < TOT) {
        int b = i / (6890 * 3);
        int r = i - b * (6890 * 3);
        int u = r / 3;
        int k = r - u * 3;
        int v = read_idx(perm, u);
        out[i] = h[(size_t)(v * 128 + b) * 3 + k];
    }
}

// ---------------------------------------------------------------------------
extern "C" void kernel_launch(void* const* d_in, const int* in_sizes, int n_in,
                              void* d_out, int out_size) {
    const float* x   = (const float*)d_in[0];
    const float* fw1 = (const float*)d_in[1];
    const float* fb1 = (const float*)d_in[2];
    const float* fw2 = (const float*)d_in[3];
    const float* fb2 = (const float*)d_in[4];
    const float* W[5];
    const float* bb[5];
    for (int i = 0; i < 5; i++) {
        W[i]  = (const float*)d_in[5 + 2 * i];
        bb[i] = (const float*)d_in[6 + 2 * i];
    }
    const void* edges[4];
    for (int i = 0; i < 4; i++) edges[i] = d_in[15 + i];
    const void* perm = d_in[19];
    float* out = (float*)d_out;

    float *T, *OA, *YB, *H1, *WC;
    __half *AH, *AL, *WTH, *WTL, *H1H, *H1L;
    cudaGetSymbolAddress((void**)&T,   g_T);
    cudaGetSymbolAddress((void**)&OA,  g_outA);
    cudaGetSymbolAddress((void**)&YB,  g_Y);
    cudaGetSymbolAddress((void**)&H1,  g_h1);
    cudaGetSymbolAddress((void**)&WC,  g_wc);
    cudaGetSymbolAddress((void**)&AH,  g_Ah);
    cudaGetSymbolAddress((void**)&AL,  g_Al);
    cudaGetSymbolAddress((void**)&WTH, g_wth);
    cudaGetSymbolAddress((void**)&WTL, g_wtl);
    cudaGetSymbolAddress((void**)&H1H, g_h1h);
    cudaGetSymbolAddress((void**)&H1L, g_h1l);

    const int DSM2 = 2 * 40960;   // 80KB, 2-split kernels
    const int DSM3 = 2 * 49152;   // 96KB, 3-split kernels
    cudaFuncSetAttribute(gemm_mmab<64, 2>,
                         cudaFuncAttributeMaxDynamicSharedMemorySize, DSM2);
    cudaFuncSetAttribute(gemm_mmab<64, 3>,
                         cudaFuncAttributeMaxDynamicSharedMemorySize, DSM3);
    cudaFuncSetAttribute(gemm_mmab<32, 3>,
                         cudaFuncAttributeMaxDynamicSharedMemorySize, DSM3);
    cudaFuncSetAttribute(gemm_fc2d,
                         cudaFuncAttributeMaxDynamicSharedMemorySize, DSM2);

    const int ns[5]   = {864, 1728, 3456, 6912, 6912};
    const int cis[5]  = {128, 128, 64, 32, 16};
    const int cos_[5] = {128, 64, 32, 16, 3};
    const int col2[5] = {7, 6, 5, 4, 0};
    const int nbArr[5] = {0, 864, 2592, 6048, 6048};
    const int npArr[5] = {384, 192, 128, 64, 0};
    const int woff[5]  = {0, 49152, 73728, 81920, 0};

    // 0: dtype sniff
    detect_kernel<<<1, 256>>>((const int*)edges[0], 5184);
    // 1: FC1 (SIMT)
    gemm_k<128, 128, 8, 8, 1><<<dim3(4, 1), 256>>>(x, fw1, fb1, H1,
                                                   128, 512, 128, 0, 0);
    // 2: split FC1 output (fp16)
    hsplit_kernel<<<256, 256>>>(H1, H1H, H1L);
    // 3: FC2 GEMM, direct fp32 B, fp16 2-split — ncu capture target
    gemm_fc2d<<<dim3(110592 / 64, 1), 256, DSM2>>>(
        H1H, H1L, fw2, fb2, AH, AL, 128, 110592, 512);
    // 4: ALL combined weights in one launch
    wprep_all<<<dim3(192, 5), 256>>>(W[0], W[1], W[2], W[3], W[4],
                                     WTH, WTL, WC);
    // 5: layer-0 ChebConv GEMM (fp16 2-split)
    gemm_mmab<64, 2><<<dim3(6, 864), 256, DSM2>>>(AH, AL, WTH, WTL, T,
                                                  110592, 384, 128, 7, 14155776LL);
    // 6-10: fused CSR build
    csr_zero_kernel<<<(12960 + 255) / 256, 256>>>();
    csr_count_kernel<<<dim3(162, 4), 256>>>(edges[0], edges[1], edges[2], edges[3]);
    csr_dinv_kernel<<<(12960 + 255) / 256, 256>>>();
    csr_scan_kernel<<<4, 1024>>>();
    csr_fill_kernel<<<dim3(162, 4), 256>>>(edges[0], edges[1], edges[2], edges[3]);

    for (int l = 0; l < 5; l++) {
        int n  = ns[l];
        int ci = cis[l];
        int co = cos_[l];
        int N  = 3 * co;
        int Np = npArr[l];
        int ng = (l == 0 || l == 4) ? n : n / 2;   // layers 1-3 un-repeated
        int Mg = ng * 128;
        int shU = (l == 0 || l == 4) ? 0 : 1;
        int R4 = 32 * co;
        long long US = (long long)Mg * co;
        int nb = nbArr[l];

        if (l > 0) {
            if (l < 4) {   // fp16 mma path (3-split)
                if (ci % 64 == 0)
                    gemm_mmab<64, 3><<<dim3(Np / 64, Mg / 128), 256, DSM3>>>(
                        AH, AL, WTH + woff[l], WTL + woff[l], T,
                        Mg, N, ci, col2[l], US);
                else
                    gemm_mmab<32, 3><<<dim3(Np / 64, Mg / 128), 256, DSM3>>>(
                        AH, AL, WTH + woff[l], WTL + woff[l], T,
                        Mg, N, ci, col2[l], US);
            } else {       // L4: K=16, SIMT fp32
                gemm_k<256, 64, 16, 4, 3><<<dim3(1, Mg / 256), 256>>>(
                    OA, WC, nullptr, T, Mg, N, ci, co, US);
            }
        }

        // Y = U1' + 2*P*U2'
        propY_kernel<<<dim3(R4 >= 256 ? R4 / 256 : 1, n), R4 < 256 ? R4 : 256>>>(
            (float4*)YB, (const float4*)(T + US), (const float4*)(T + 2 * US),
            R4, shU, nb);
        // out = act(U0' + P*Y + b)
        if (l < 3) {
            propF_kernel<1><<<dim3(R4 / 256, n), 256>>>(
                nullptr, AH, AL, (const float4*)T, (const float4*)YB,
                bb[l], R4, co - 1, shU, nb);
        } else if (l == 3) {
            propF_kernel<0><<<dim3(R4 / 256, n), 256>>>(
                OA, nullptr, nullptr, (const float4*)T, (const float4*)YB,
                bb[l], R4, co - 1, shU, nb);
        } else {
            propF3_kernel<<<dim3(3, n), 128>>>(OA, T, YB, bb[4], nb);
        }
    }

    const int TOT = 128 * 6890 * 3;
    final_kernel<<<(TOT + 255) / 256, 256>>>(out, OA, perm);
}